// round 1
// baseline (speedup 1.0000x reference)
#include <cuda_runtime.h>
#include <math.h>
#include <math_constants.h>

// Problem constants (fixed by the dataset)
#define B_     8
#define NTOK   1024
#define DIM    512
#define HEADS  16
#define HD     32
#define TBL    3969
#define CPBH   512

// ---------------- scratch (device globals; no dynamic allocation) ----------
__device__ float g_qkv[B_ * NTOK * 3 * DIM];          // 50.3 MB  raw qkv
__device__ float g_q  [B_ * HEADS * NTOK * HD];        // 16.8 MB  normed+scaled q
__device__ float g_k  [B_ * HEADS * NTOK * HD];        // 16.8 MB  normed k
__device__ float g_v  [B_ * HEADS * NTOK * HD];        // 16.8 MB  v
__device__ float g_att[B_ * NTOK * DIM];               // 16.8 MB  attention output
__device__ float g_tt [HEADS * TBL];                   // 254 KB   cpb table, [h][tbl]

// ---------------------------------------------------------------------------
// Kernel 1: continuous position bias MLP.
// t = relu(table @ fc1_w^T + b1) @ fc2_w^T + b2 ; store transposed tt[h][r].
// ---------------------------------------------------------------------------
__global__ __launch_bounds__(512)
void cpb_kernel(const float* __restrict__ tbl,   // [TBL][2]
                const float* __restrict__ w1,    // [512][2]
                const float* __restrict__ b1,    // [512]
                const float* __restrict__ w2,    // [16][512]
                const float* __restrict__ b2,    // [16]
                float* __restrict__ tt)          // [16][TBL]
{
    __shared__ float hid[512];
    const int r = blockIdx.x;
    const int tid = threadIdx.x;
    const float c0 = tbl[r * 2 + 0];
    const float c1 = tbl[r * 2 + 1];
    hid[tid] = fmaxf(fmaf(c0, w1[tid * 2 + 0], fmaf(c1, w1[tid * 2 + 1], b1[tid])), 0.0f);
    __syncthreads();
    const int w = tid >> 5, lane = tid & 31;
    float s = 0.0f;
#pragma unroll
    for (int i = 0; i < 512; i += 32)
        s = fmaf(hid[i + lane], w2[w * 512 + i + lane], s);
#pragma unroll
    for (int msk = 16; msk >= 1; msk >>= 1)
        s += __shfl_xor_sync(0xffffffffu, s, msk);
    if (lane == 0)
        tt[w * TBL + r] = s + b2[w];
}

// ---------------------------------------------------------------------------
// Kernel 2/5: fp32 NT-SGEMM.  C[M][N] = A[M][K] @ B[N][K]^T + bias[N]
// 128x128 tile, BK=8, 256 threads, 8x8 register tile per thread.
// ---------------------------------------------------------------------------
__global__ __launch_bounds__(256)
void sgemm_nt(const float* __restrict__ A, const float* __restrict__ Bm,
              const float* __restrict__ bias, float* __restrict__ C,
              int M, int N, int K)
{
    __shared__ float As[8][128];
    __shared__ float Bs[8][128];
    const int tid  = threadIdx.x;
    const int tx   = tid & 15, ty = tid >> 4;
    const int row0 = blockIdx.y * 128;
    const int col0 = blockIdx.x * 128;
    const int lr   = tid >> 1;
    const int lk   = (tid & 1) * 4;

    const float* Ap = A  + (size_t)(row0 + lr) * K + lk;
    const float* Bp = Bm + (size_t)(col0 + lr) * K + lk;

    float acc[8][8];
#pragma unroll
    for (int i = 0; i < 8; i++)
#pragma unroll
        for (int j = 0; j < 8; j++) acc[i][j] = 0.0f;

    for (int kt = 0; kt < K; kt += 8) {
        const float4 a4 = *(const float4*)(Ap + kt);
        const float4 b4 = *(const float4*)(Bp + kt);
        __syncthreads();
        As[lk + 0][lr] = a4.x; As[lk + 1][lr] = a4.y;
        As[lk + 2][lr] = a4.z; As[lk + 3][lr] = a4.w;
        Bs[lk + 0][lr] = b4.x; Bs[lk + 1][lr] = b4.y;
        Bs[lk + 2][lr] = b4.z; Bs[lk + 3][lr] = b4.w;
        __syncthreads();
#pragma unroll
        for (int kk = 0; kk < 8; kk++) {
            const float4 a0 = *(const float4*)&As[kk][ty * 8];
            const float4 a1 = *(const float4*)&As[kk][ty * 8 + 4];
            const float4 b0 = *(const float4*)&Bs[kk][tx * 8];
            const float4 b1 = *(const float4*)&Bs[kk][tx * 8 + 4];
            const float ar[8] = {a0.x, a0.y, a0.z, a0.w, a1.x, a1.y, a1.z, a1.w};
            const float br[8] = {b0.x, b0.y, b0.z, b0.w, b1.x, b1.y, b1.z, b1.w};
#pragma unroll
            for (int i = 0; i < 8; i++)
#pragma unroll
                for (int j = 0; j < 8; j++)
                    acc[i][j] = fmaf(ar[i], br[j], acc[i][j]);
        }
    }

#pragma unroll
    for (int i = 0; i < 8; i++) {
        const int row = row0 + ty * 8 + i;
        float* Cp = C + (size_t)row * N + col0 + tx * 8;
        const float* bp = bias + col0 + tx * 8;
#pragma unroll
        for (int j = 0; j < 8; j += 4) {
            float4 o;
            o.x = acc[i][j + 0] + bp[j + 0];
            o.y = acc[i][j + 1] + bp[j + 1];
            o.z = acc[i][j + 2] + bp[j + 2];
            o.w = acc[i][j + 3] + bp[j + 3];
            *(float4*)(Cp + j) = o;
        }
    }
}

// ---------------------------------------------------------------------------
// Kernel 3: split qkv + l2norm + query-embedding + temperature scale.
// One block (512 threads) per token; warp h handles head h (32 dims).
// ---------------------------------------------------------------------------
__global__ __launch_bounds__(512)
void qkv_norm_kernel(const float* __restrict__ raw,    // [B*N][1536]
                     const float* __restrict__ temp,   // [16]
                     const float* __restrict__ qe,     // [16][32]
                     const float* __restrict__ sls,    // [1]
                     float* __restrict__ Q, float* __restrict__ K,
                     float* __restrict__ V)
{
    const int row = blockIdx.x;                 // b*1024+n
    const int b = row >> 10, n = row & 1023;
    const int tid = threadIdx.x;
    const int h = tid >> 5, lane = tid & 31;
    const size_t base = (size_t)row * (3 * DIM);

    const float qv = raw[base + tid];
    const float kv = raw[base + DIM + tid];
    const float vv = raw[base + 2 * DIM + tid];

    float sq = qv * qv;
#pragma unroll
    for (int msk = 16; msk >= 1; msk >>= 1) sq += __shfl_xor_sync(0xffffffffu, sq, msk);
    float qn = qv / fmaxf(sqrtf(sq), 1e-12f);
    const float scale = log1pf(expf(temp[h])) * sls[0];
    qn = (qn + qe[h * HD + lane]) * scale;

    float sk = kv * kv;
#pragma unroll
    for (int msk = 16; msk >= 1; msk >>= 1) sk += __shfl_xor_sync(0xffffffffu, sk, msk);
    const float kn = kv / fmaxf(sqrtf(sk), 1e-12f);

    const size_t oidx = ((((size_t)b * HEADS) + h) * NTOK + n) * HD + lane;
    Q[oidx] = qn;
    K[oidx] = kn;
    V[oidx] = vv;
}

// ---------------------------------------------------------------------------
// Kernel 4: fused flash attention with gathered relative bias.
// Block = one (b, h, 64-query tile); loops over 16 key tiles of 64.
// S = Qn Kn^T + tt[h][idx[n*1024+m]], online softmax, O += P V.
// ---------------------------------------------------------------------------
__global__ __launch_bounds__(256)
void attn_kernel(const float* __restrict__ Qg_, const float* __restrict__ Kg_,
                 const float* __restrict__ Vg_, const int* __restrict__ idx,
                 const float* __restrict__ tt, float* __restrict__ outp)
{
    __shared__ float Qs[32][68];   // Q^T tile
    __shared__ float Ks[32][68];   // K^T tile
    __shared__ float Vs[64][36];   // V tile
    __shared__ float Ps[64][68];   // P tile

    const int tid = threadIdx.x;
    const int tx = tid & 15, ty = tid >> 4;
    const int q0 = blockIdx.x * 64;
    const int h  = blockIdx.y;
    const int b  = blockIdx.z;
    const size_t bh = (((size_t)b * HEADS) + h) * NTOK * HD;
    const float* Qg = Qg_ + bh;
    const float* Kg = Kg_ + bh;
    const float* Vg = Vg_ + bh;
    const float* ttg = tt + h * TBL;

    // load Q tile transposed
    {
        const int r  = tid >> 2;
        const int d0 = (tid & 3) * 8;
        const float* qp = Qg + (size_t)(q0 + r) * HD + d0;
        const float4 v0 = *(const float4*)qp;
        const float4 v1 = *(const float4*)(qp + 4);
        Qs[d0 + 0][r] = v0.x; Qs[d0 + 1][r] = v0.y; Qs[d0 + 2][r] = v0.z; Qs[d0 + 3][r] = v0.w;
        Qs[d0 + 4][r] = v1.x; Qs[d0 + 5][r] = v1.y; Qs[d0 + 6][r] = v1.z; Qs[d0 + 7][r] = v1.w;
    }

    const int r0 = ty * 4, c0 = tx * 4;
    float m[4] = {-CUDART_INF_F, -CUDART_INF_F, -CUDART_INF_F, -CUDART_INF_F};
    float l[4] = {0.f, 0.f, 0.f, 0.f};
    float o0[4] = {0.f, 0.f, 0.f, 0.f};
    float o1[4] = {0.f, 0.f, 0.f, 0.f};

    const int lr  = tid >> 2;
    const int ld0 = (tid & 3) * 8;

    for (int kt = 0; kt < NTOK; kt += 64) {
        __syncthreads();   // previous tile's Ps/Vs/Ks consumers done
        {
            const float* kp = Kg + (size_t)(kt + lr) * HD + ld0;
            const float4 k0 = *(const float4*)kp;
            const float4 k1 = *(const float4*)(kp + 4);
            Ks[ld0 + 0][lr] = k0.x; Ks[ld0 + 1][lr] = k0.y;
            Ks[ld0 + 2][lr] = k0.z; Ks[ld0 + 3][lr] = k0.w;
            Ks[ld0 + 4][lr] = k1.x; Ks[ld0 + 5][lr] = k1.y;
            Ks[ld0 + 6][lr] = k1.z; Ks[ld0 + 7][lr] = k1.w;
            const float* vp = Vg + (size_t)(kt + lr) * HD + ld0;
            *(float4*)&Vs[lr][ld0]     = *(const float4*)vp;
            *(float4*)&Vs[lr][ld0 + 4] = *(const float4*)(vp + 4);
        }
        __syncthreads();

        // ---- S = Q K^T (4x4 per thread) ----
        float s[4][4];
#pragma unroll
        for (int i = 0; i < 4; i++)
#pragma unroll
            for (int j = 0; j < 4; j++) s[i][j] = 0.0f;
#pragma unroll
        for (int d = 0; d < 32; d++) {
            const float4 qa = *(const float4*)&Qs[d][r0];
            const float4 kb = *(const float4*)&Ks[d][c0];
            s[0][0] = fmaf(qa.x, kb.x, s[0][0]); s[0][1] = fmaf(qa.x, kb.y, s[0][1]);
            s[0][2] = fmaf(qa.x, kb.z, s[0][2]); s[0][3] = fmaf(qa.x, kb.w, s[0][3]);
            s[1][0] = fmaf(qa.y, kb.x, s[1][0]); s[1][1] = fmaf(qa.y, kb.y, s[1][1]);
            s[1][2] = fmaf(qa.y, kb.z, s[1][2]); s[1][3] = fmaf(qa.y, kb.w, s[1][3]);
            s[2][0] = fmaf(qa.z, kb.x, s[2][0]); s[2][1] = fmaf(qa.z, kb.y, s[2][1]);
            s[2][2] = fmaf(qa.z, kb.z, s[2][2]); s[2][3] = fmaf(qa.z, kb.w, s[2][3]);
            s[3][0] = fmaf(qa.w, kb.x, s[3][0]); s[3][1] = fmaf(qa.w, kb.y, s[3][1]);
            s[3][2] = fmaf(qa.w, kb.z, s[3][2]); s[3][3] = fmaf(qa.w, kb.w, s[3][3]);
        }

        // ---- gathered relative position bias ----
#pragma unroll
        for (int ri = 0; ri < 4; ri++) {
            const int4 id4 = *(const int4*)(idx + (size_t)(q0 + r0 + ri) * NTOK + kt + c0);
            s[ri][0] += ttg[id4.x];
            s[ri][1] += ttg[id4.y];
            s[ri][2] += ttg[id4.z];
            s[ri][3] += ttg[id4.w];
        }

        // ---- online softmax (row stats across the 16 tx lanes) ----
#pragma unroll
        for (int ri = 0; ri < 4; ri++) {
            float rm = fmaxf(fmaxf(s[ri][0], s[ri][1]), fmaxf(s[ri][2], s[ri][3]));
#pragma unroll
            for (int msk = 8; msk >= 1; msk >>= 1)
                rm = fmaxf(rm, __shfl_xor_sync(0xffffffffu, rm, msk));
            const float mn = fmaxf(m[ri], rm);
            const float cf = __expf(m[ri] - mn);
            o0[ri] *= cf; o1[ri] *= cf;
            const float p0 = __expf(s[ri][0] - mn);
            const float p1 = __expf(s[ri][1] - mn);
            const float p2 = __expf(s[ri][2] - mn);
            const float p3 = __expf(s[ri][3] - mn);
            *(float4*)&Ps[r0 + ri][c0] = make_float4(p0, p1, p2, p3);
            float rs = (p0 + p1) + (p2 + p3);
#pragma unroll
            for (int msk = 8; msk >= 1; msk >>= 1)
                rs += __shfl_xor_sync(0xffffffffu, rs, msk);
            l[ri] = l[ri] * cf + rs;
            m[ri] = mn;
        }
        __syncthreads();

        // ---- O += P V (each thread: 4 rows x dims {2tx, 2tx+1}) ----
        const int dv = 2 * tx;
#pragma unroll
        for (int j = 0; j < 64; j += 4) {
            const float2 va = *(const float2*)&Vs[j + 0][dv];
            const float2 vb = *(const float2*)&Vs[j + 1][dv];
            const float2 vc = *(const float2*)&Vs[j + 2][dv];
            const float2 vd = *(const float2*)&Vs[j + 3][dv];
#pragma unroll
            for (int ri = 0; ri < 4; ri++) {
                const float4 p = *(const float4*)&Ps[r0 + ri][j];
                o0[ri] = fmaf(p.x, va.x, fmaf(p.y, vb.x, fmaf(p.z, vc.x, fmaf(p.w, vd.x, o0[ri]))));
                o1[ri] = fmaf(p.x, va.y, fmaf(p.y, vb.y, fmaf(p.z, vc.y, fmaf(p.w, vd.y, o1[ri]))));
            }
        }
    }

    // ---- epilogue: normalize, write [B][N][h*32+d] ----
#pragma unroll
    for (int ri = 0; ri < 4; ri++) {
        const float inv = 1.0f / l[ri];
        const int n = q0 + r0 + ri;
        const float2 o = make_float2(o0[ri] * inv, o1[ri] * inv);
        *(float2*)(outp + ((size_t)b * NTOK + n) * DIM + h * HD + 2 * tx) = o;
    }
}

// ---------------------------------------------------------------------------
extern "C" void kernel_launch(void* const* d_in, const int* in_sizes, int n_in,
                              void* d_out, int out_size)
{
    (void)in_sizes; (void)n_in; (void)out_size;
    const float* x      = (const float*)d_in[0];
    const float* qkv_w  = (const float*)d_in[1];
    const float* qkv_b  = (const float*)d_in[2];
    const float* proj_w = (const float*)d_in[3];
    const float* proj_b = (const float*)d_in[4];
    const float* temp   = (const float*)d_in[5];
    const float* qe     = (const float*)d_in[6];
    const float* c1w    = (const float*)d_in[7];
    const float* c1b    = (const float*)d_in[8];
    const float* c2w    = (const float*)d_in[9];
    const float* c2b    = (const float*)d_in[10];
    const float* rct    = (const float*)d_in[11];
    const int*   rpi    = (const int*)d_in[12];
    const float* sls    = (const float*)d_in[13];
    // d_in[14] padding_mask (all false, unused by reference), d_in[15] H, d_in[16] W unused
    float* out = (float*)d_out;

    float *qkv_s, *q_s, *k_s, *v_s, *att_s, *tt_s;
    cudaGetSymbolAddress((void**)&qkv_s, g_qkv);
    cudaGetSymbolAddress((void**)&q_s,   g_q);
    cudaGetSymbolAddress((void**)&k_s,   g_k);
    cudaGetSymbolAddress((void**)&v_s,   g_v);
    cudaGetSymbolAddress((void**)&att_s, g_att);
    cudaGetSymbolAddress((void**)&tt_s,  g_tt);

    // 1. CPB MLP
    cpb_kernel<<<TBL, 512>>>(rct, c1w, c1b, c2w, c2b, tt_s);

    // 2. qkv projection: [8192,512] x [1536,512]^T
    sgemm_nt<<<dim3(12, 64), 256>>>(x, qkv_w, qkv_b, qkv_s,
                                    B_ * NTOK, 3 * DIM, DIM);

    // 3. split + normalize
    qkv_norm_kernel<<<B_ * NTOK, 512>>>(qkv_s, temp, qe, sls, q_s, k_s, v_s);

    // 4. fused attention
    attn_kernel<<<dim3(NTOK / 64, HEADS, B_), 256>>>(q_s, k_s, v_s, rpi, tt_s, att_s);

    // 5. output projection: [8192,512] x [512,512]^T
    sgemm_nt<<<dim3(4, 64), 256>>>(att_s, proj_w, proj_b, out,
                                   B_ * NTOK, DIM, DIM);
}

// round 2
// speedup vs baseline: 1.4762x; 1.4762x over previous
#include <cuda_runtime.h>
#include <cstdint>
#include <math.h>
#include <math_constants.h>

#define B_     8
#define NTOK   1024
#define DIM    512
#define HEADS  16
#define HD     32
#define TBL    3969

// ---------------- scratch (device globals; no dynamic allocation) ----------
__device__ float g_qkv[B_ * NTOK * 3 * DIM];           // raw qkv
__device__ float g_q  [B_ * HEADS * NTOK * HD];
__device__ float g_k  [B_ * HEADS * NTOK * HD];
__device__ float g_v  [B_ * HEADS * NTOK * HD];
__device__ float g_att[B_ * NTOK * DIM];
__device__ float g_tt [HEADS * TBL];
__device__ float g_rb [HEADS * NTOK * NTOK];           // 67MB materialized bias

// ---------------------------------------------------------------------------
// helpers: tf32 mma + conversions + cp.async
// ---------------------------------------------------------------------------
__device__ __forceinline__ unsigned cvt_tf32(float x) {
    unsigned r;
    asm("cvt.rna.tf32.f32 %0, %1;" : "=r"(r) : "f"(x));
    return r;
}
__device__ __forceinline__ void cvt_hilo(float x, unsigned& hi, unsigned& lo) {
    hi = cvt_tf32(x);
    lo = cvt_tf32(x - __uint_as_float(hi));
}
__device__ __forceinline__ void mma8(float* d, const unsigned* a, unsigned b0, unsigned b1) {
    asm volatile("mma.sync.aligned.m16n8k8.row.col.f32.tf32.tf32.f32 "
                 "{%0,%1,%2,%3}, {%4,%5,%6,%7}, {%8,%9}, {%0,%1,%2,%3};"
                 : "+f"(d[0]), "+f"(d[1]), "+f"(d[2]), "+f"(d[3])
                 : "r"(a[0]), "r"(a[1]), "r"(a[2]), "r"(a[3]), "r"(b0), "r"(b1));
}
__device__ __forceinline__ void cp16(uint32_t dst, const float* src) {
    asm volatile("cp.async.cg.shared.global [%0], [%1], 16;" :: "r"(dst), "l"(src));
}
#define CP_COMMIT() asm volatile("cp.async.commit_group;" ::: "memory")
#define CP_WAIT1()  asm volatile("cp.async.wait_group 1;" ::: "memory")
#define CP_WAIT0()  asm volatile("cp.async.wait_group 0;" ::: "memory")

// ---------------------------------------------------------------------------
// Kernel 1: continuous position bias MLP  (unchanged)
// ---------------------------------------------------------------------------
__global__ __launch_bounds__(512)
void cpb_kernel(const float* __restrict__ tbl, const float* __restrict__ w1,
                const float* __restrict__ b1, const float* __restrict__ w2,
                const float* __restrict__ b2, float* __restrict__ tt)
{
    __shared__ float hid[512];
    const int r = blockIdx.x;
    const int tid = threadIdx.x;
    const float c0 = tbl[r * 2 + 0];
    const float c1 = tbl[r * 2 + 1];
    hid[tid] = fmaxf(fmaf(c0, w1[tid * 2 + 0], fmaf(c1, w1[tid * 2 + 1], b1[tid])), 0.0f);
    __syncthreads();
    const int w = tid >> 5, lane = tid & 31;
    float s = 0.0f;
#pragma unroll
    for (int i = 0; i < 512; i += 32)
        s = fmaf(hid[i + lane], w2[w * 512 + i + lane], s);
#pragma unroll
    for (int msk = 16; msk >= 1; msk >>= 1)
        s += __shfl_xor_sync(0xffffffffu, s, msk);
    if (lane == 0)
        tt[w * TBL + r] = s + b2[w];
}

// ---------------------------------------------------------------------------
// Kernel 2: materialize rb[h][q][k] = tt[h][idx[q*1024+k]]
// ---------------------------------------------------------------------------
__global__ __launch_bounds__(256)
void rb_kernel(const int* __restrict__ idx, const float* __restrict__ tt,
               float* __restrict__ rb)
{
    const int q = blockIdx.x, h = blockIdx.y;
    const int k = threadIdx.x * 4;
    const int4 id = *(const int4*)(idx + q * NTOK + k);
    const float* tth = tt + h * TBL;
    float4 o = make_float4(tth[id.x], tth[id.y], tth[id.z], tth[id.w]);
    *(float4*)(rb + ((size_t)h * NTOK + q) * NTOK + k) = o;
}

// ---------------------------------------------------------------------------
// Kernel 3/6: 3xTF32 tensor-core NT-GEMM.  C = A[M][K] @ B[N][K]^T + bias[N]
// 128x128 tile, k-step 16, 256 threads / 8 warps (2m x 4n), cp.async 2-stage.
// ---------------------------------------------------------------------------
#define GLD 20   // padded smem row stride (conflict-free fragment loads)

__global__ __launch_bounds__(256, 2)
void gemm3t(const float* __restrict__ A, const float* __restrict__ Bm,
            const float* __restrict__ bias, float* __restrict__ C,
            int M, int N, int K)
{
    __shared__ float As[2][128 * GLD];
    __shared__ float Bs[2][128 * GLD];

    const int tid = threadIdx.x;
    const int w = tid >> 5, lane = tid & 31;
    const int gid = lane >> 2, tig = lane & 3;
    const int wm = w >> 2, wn = w & 3;
    const int row0 = blockIdx.y * 128, col0 = blockIdx.x * 128;
    const int NS = K / 16;

    const uint32_t as0 = (uint32_t)__cvta_generic_to_shared(&As[0][0]);
    const uint32_t bs0 = (uint32_t)__cvta_generic_to_shared(&Bs[0][0]);

    float acc[4][4][4];
#pragma unroll
    for (int i = 0; i < 4; i++)
#pragma unroll
        for (int j = 0; j < 4; j++)
#pragma unroll
            for (int q = 0; q < 4; q++) acc[i][j][q] = 0.0f;

    // async tile loader: 512 float4 slots per matrix, 2 per thread
#define GEMM_LOAD(s, buf)                                                        \
    {                                                                            \
        const int k0_ = (s) * 16;                                                \
        _Pragma("unroll")                                                        \
        for (int i_ = 0; i_ < 2; i_++) {                                         \
            const int slot_ = tid + i_ * 256;                                    \
            const int r_ = slot_ >> 2, q_ = slot_ & 3;                           \
            const uint32_t off_ = ((buf) * 128 * GLD + r_ * GLD + q_ * 4) * 4;   \
            cp16(as0 + off_, A  + (size_t)(row0 + r_) * K + k0_ + q_ * 4);       \
            cp16(bs0 + off_, Bm + (size_t)(col0 + r_) * K + k0_ + q_ * 4);       \
        }                                                                        \
        CP_COMMIT();                                                             \
    }

    GEMM_LOAD(0, 0);
    GEMM_LOAD(1, 1);

    for (int s = 0; s < NS; s++) {
        if (s < NS - 1) { CP_WAIT1(); } else { CP_WAIT0(); }
        __syncthreads();
        const float* a_s = As[s & 1];
        const float* b_s = Bs[s & 1];
#pragma unroll
        for (int k8 = 0; k8 < 2; k8++) {
            const int kk = k8 * 8;
            unsigned ahi[4][4], alo[4][4];
#pragma unroll
            for (int mt = 0; mt < 4; mt++) {
                const float* ap = a_s + (wm * 64 + mt * 16) * GLD + kk;
                cvt_hilo(ap[gid * GLD + tig],           ahi[mt][0], alo[mt][0]);
                cvt_hilo(ap[(gid + 8) * GLD + tig],     ahi[mt][1], alo[mt][1]);
                cvt_hilo(ap[gid * GLD + tig + 4],       ahi[mt][2], alo[mt][2]);
                cvt_hilo(ap[(gid + 8) * GLD + tig + 4], ahi[mt][3], alo[mt][3]);
            }
#pragma unroll
            for (int nt = 0; nt < 4; nt++) {
                const float* bp = b_s + (wn * 32 + nt * 8) * GLD + kk;
                unsigned bh0, bl0, bh1, bl1;
                cvt_hilo(bp[gid * GLD + tig],     bh0, bl0);
                cvt_hilo(bp[gid * GLD + tig + 4], bh1, bl1);
#pragma unroll
                for (int mt = 0; mt < 4; mt++) {
                    mma8(acc[mt][nt], ahi[mt], bh0, bh1);
                    mma8(acc[mt][nt], alo[mt], bh0, bh1);
                    mma8(acc[mt][nt], ahi[mt], bl0, bl1);
                }
            }
        }
        __syncthreads();
        if (s + 2 < NS) GEMM_LOAD(s + 2, s & 1);
    }

    // epilogue: +bias, store float2 pairs
#pragma unroll
    for (int mt = 0; mt < 4; mt++) {
        const int ra = row0 + wm * 64 + mt * 16 + gid;
#pragma unroll
        for (int nt = 0; nt < 4; nt++) {
            const int c = col0 + wn * 32 + nt * 8 + 2 * tig;
            const float bb0 = bias[c], bb1 = bias[c + 1];
            *(float2*)(C + (size_t)ra * N + c) =
                make_float2(acc[mt][nt][0] + bb0, acc[mt][nt][1] + bb1);
            *(float2*)(C + (size_t)(ra + 8) * N + c) =
                make_float2(acc[mt][nt][2] + bb0, acc[mt][nt][3] + bb1);
        }
    }
}

// ---------------------------------------------------------------------------
// Kernel 4: split qkv + l2norm + query-embedding + temperature scale (unchanged)
// ---------------------------------------------------------------------------
__global__ __launch_bounds__(512)
void qkv_norm_kernel(const float* __restrict__ raw, const float* __restrict__ temp,
                     const float* __restrict__ qe, const float* __restrict__ sls,
                     float* __restrict__ Q, float* __restrict__ K, float* __restrict__ V)
{
    const int row = blockIdx.x;
    const int b = row >> 10, n = row & 1023;
    const int tid = threadIdx.x;
    const int h = tid >> 5, lane = tid & 31;
    const size_t base = (size_t)row * (3 * DIM);

    const float qv = raw[base + tid];
    const float kv = raw[base + DIM + tid];
    const float vv = raw[base + 2 * DIM + tid];

    float sq = qv * qv;
#pragma unroll
    for (int msk = 16; msk >= 1; msk >>= 1) sq += __shfl_xor_sync(0xffffffffu, sq, msk);
    float qn = qv / fmaxf(sqrtf(sq), 1e-12f);
    const float scale = log1pf(expf(temp[h])) * sls[0];
    qn = (qn + qe[h * HD + lane]) * scale;

    float sk = kv * kv;
#pragma unroll
    for (int msk = 16; msk >= 1; msk >>= 1) sk += __shfl_xor_sync(0xffffffffu, sk, msk);
    const float kn = kv / fmaxf(sqrtf(sk), 1e-12f);

    const size_t oidx = ((((size_t)b * HEADS) + h) * NTOK + n) * HD + lane;
    Q[oidx] = qn;
    K[oidx] = kn;
    V[oidx] = vv;
}

// ---------------------------------------------------------------------------
// Kernel 5: tensor-core flash attention.
// Block = (b, h, 128-query tile), 8 warps x 16 rows. Key tiles of 64.
// S = rb + Q K^T (3xTF32), online softmax, O += P V (2xTF32), cp.async K/V.
// smem: K 2x(64x36), V 2x(64x36), P per-warp 16x68.
// ---------------------------------------------------------------------------
#define KLD 36
#define PLD 68
#define ATTN_SMEM ((2 * 64 * KLD * 2 + 8 * 16 * PLD) * 4)

__global__ __launch_bounds__(256, 2)
void attn_mma(const float* __restrict__ Qg_, const float* __restrict__ Kg_,
              const float* __restrict__ Vg_, const float* __restrict__ rb,
              float* __restrict__ outp)
{
    extern __shared__ float sm[];
    float* Kbuf = sm;                       // 2 * 64*KLD
    float* Vbuf = sm + 2 * 64 * KLD;        // 2 * 64*KLD
    float* Pb   = sm + 4 * 64 * KLD;        // 8 * 16*PLD

    const int tid = threadIdx.x;
    const int w = tid >> 5, lane = tid & 31;
    const int gid = lane >> 2, tig = lane & 3;
    const int q0 = blockIdx.x * 128, h = blockIdx.y, b = blockIdx.z;
    const size_t bh = ((size_t)b * HEADS + h) * NTOK * HD;
    const float* Qg = Qg_ + bh;
    const float* Kg = Kg_ + bh;
    const float* Vg = Vg_ + bh;
    const float* rbh = rb + (size_t)h * NTOK * NTOK;
    float* Pw = Pb + w * 16 * PLD;
    const int r0 = q0 + w * 16 + gid;
    const int r1 = r0 + 8;

    const uint32_t smb = (uint32_t)__cvta_generic_to_shared(sm);

    // Q fragments (hi/lo), loaded once
    unsigned qhi[4][4], qlo[4][4];
#pragma unroll
    for (int kt = 0; kt < 4; kt++) {
        cvt_hilo(Qg[(size_t)r0 * HD + kt * 8 + tig],     qhi[kt][0], qlo[kt][0]);
        cvt_hilo(Qg[(size_t)r1 * HD + kt * 8 + tig],     qhi[kt][1], qlo[kt][1]);
        cvt_hilo(Qg[(size_t)r0 * HD + kt * 8 + tig + 4], qhi[kt][2], qlo[kt][2]);
        cvt_hilo(Qg[(size_t)r1 * HD + kt * 8 + tig + 4], qhi[kt][3], qlo[kt][3]);
    }

    float o[4][4];
#pragma unroll
    for (int i = 0; i < 4; i++)
#pragma unroll
        for (int j = 0; j < 4; j++) o[i][j] = 0.0f;
    float m0 = -CUDART_INF_F, m1 = -CUDART_INF_F, l0 = 0.0f, l1 = 0.0f;

    // async K/V tile loader: 512 float4 slots per matrix; threads 0-127 -> K,
    // 128-255 -> V; 4 cp.async each, fully coalesced.
#define ATTN_LOAD(t, buf)                                                          \
    {                                                                              \
        const int key0_ = (t) * 64;                                               \
        const float* src_ = (tid < 128) ? Kg : Vg;                                 \
        const uint32_t base_ = smb + ((tid < 128) ? 0u : (uint32_t)(2*64*KLD*4))   \
                               + (uint32_t)((buf) * 64 * KLD * 4);                 \
        const int t2_ = tid & 127;                                                 \
        _Pragma("unroll")                                                          \
        for (int i_ = 0; i_ < 4; i_++) {                                           \
            const int slot_ = t2_ + i_ * 128;                                      \
            const int r_ = slot_ >> 3, q_ = slot_ & 7;                             \
            cp16(base_ + (uint32_t)((r_ * KLD + q_ * 4) * 4),                      \
                 src_ + (size_t)(key0_ + r_) * HD + q_ * 4);                       \
        }                                                                          \
        CP_COMMIT();                                                               \
    }

    ATTN_LOAD(0, 0);
    ATTN_LOAD(1, 1);

    for (int t = 0; t < 16; t++) {
        if (t < 15) { CP_WAIT1(); } else { CP_WAIT0(); }
        __syncthreads();
        const float* Ks = Kbuf + (t & 1) * 64 * KLD;
        const float* Vs = Vbuf + (t & 1) * 64 * KLD;
        const int key0 = t * 64;

        // ---- S accumulators initialized with bias (issued early to hide latency)
        float s[8][4];
#pragma unroll
        for (int nt = 0; nt < 8; nt++) {
            const float2 u0 = *(const float2*)(rbh + (size_t)r0 * NTOK + key0 + nt * 8 + 2 * tig);
            const float2 u1 = *(const float2*)(rbh + (size_t)r1 * NTOK + key0 + nt * 8 + 2 * tig);
            s[nt][0] = u0.x; s[nt][1] = u0.y; s[nt][2] = u1.x; s[nt][3] = u1.y;
        }
        // ---- S += Q K^T (3xTF32)
#pragma unroll
        for (int kt = 0; kt < 4; kt++) {
#pragma unroll
            for (int nt = 0; nt < 8; nt++) {
                unsigned bh0, bl0, bh1, bl1;
                cvt_hilo(Ks[(nt * 8 + gid) * KLD + kt * 8 + tig],     bh0, bl0);
                cvt_hilo(Ks[(nt * 8 + gid) * KLD + kt * 8 + tig + 4], bh1, bl1);
                mma8(s[nt], qhi[kt], bh0, bh1);
                mma8(s[nt], qlo[kt], bh0, bh1);
                mma8(s[nt], qhi[kt], bl0, bl1);
            }
        }

        // ---- online softmax (rows r0 and r1; stats across quad lanes)
        float mx0 = s[0][0], mx1 = s[0][2];
#pragma unroll
        for (int nt = 0; nt < 8; nt++) {
            mx0 = fmaxf(mx0, fmaxf(s[nt][0], s[nt][1]));
            mx1 = fmaxf(mx1, fmaxf(s[nt][2], s[nt][3]));
        }
        mx0 = fmaxf(mx0, __shfl_xor_sync(0xffffffffu, mx0, 1));
        mx0 = fmaxf(mx0, __shfl_xor_sync(0xffffffffu, mx0, 2));
        mx1 = fmaxf(mx1, __shfl_xor_sync(0xffffffffu, mx1, 1));
        mx1 = fmaxf(mx1, __shfl_xor_sync(0xffffffffu, mx1, 2));
        const float mn0 = fmaxf(m0, mx0), mn1 = fmaxf(m1, mx1);
        const float cf0 = __expf(m0 - mn0), cf1 = __expf(m1 - mn1);
        float sum0 = 0.0f, sum1 = 0.0f;
#pragma unroll
        for (int nt = 0; nt < 8; nt++) {
            s[nt][0] = __expf(s[nt][0] - mn0);
            s[nt][1] = __expf(s[nt][1] - mn0);
            s[nt][2] = __expf(s[nt][2] - mn1);
            s[nt][3] = __expf(s[nt][3] - mn1);
            sum0 += s[nt][0] + s[nt][1];
            sum1 += s[nt][2] + s[nt][3];
        }
        sum0 += __shfl_xor_sync(0xffffffffu, sum0, 1);
        sum0 += __shfl_xor_sync(0xffffffffu, sum0, 2);
        sum1 += __shfl_xor_sync(0xffffffffu, sum1, 1);
        sum1 += __shfl_xor_sync(0xffffffffu, sum1, 2);
        l0 = l0 * cf0 + sum0;
        l1 = l1 * cf1 + sum1;
        m0 = mn0; m1 = mn1;
#pragma unroll
        for (int dnt = 0; dnt < 4; dnt++) {
            o[dnt][0] *= cf0; o[dnt][1] *= cf0;
            o[dnt][2] *= cf1; o[dnt][3] *= cf1;
        }

        // ---- stage P to per-warp smem (C-frag -> A-frag reshape)
#pragma unroll
        for (int nt = 0; nt < 8; nt++) {
            *(float2*)&Pw[gid * PLD + nt * 8 + 2 * tig]       = make_float2(s[nt][0], s[nt][1]);
            *(float2*)&Pw[(gid + 8) * PLD + nt * 8 + 2 * tig] = make_float2(s[nt][2], s[nt][3]);
        }
        __syncwarp();

        // ---- O += P V  (P hi-only; V split -> 2 mmas)
#pragma unroll
        for (int kt8 = 0; kt8 < 8; kt8++) {
            unsigned pa[4];
            pa[0] = cvt_tf32(Pw[gid * PLD + kt8 * 8 + tig]);
            pa[1] = cvt_tf32(Pw[(gid + 8) * PLD + kt8 * 8 + tig]);
            pa[2] = cvt_tf32(Pw[gid * PLD + kt8 * 8 + tig + 4]);
            pa[3] = cvt_tf32(Pw[(gid + 8) * PLD + kt8 * 8 + tig + 4]);
#pragma unroll
            for (int dnt = 0; dnt < 4; dnt++) {
                unsigned vh0, vl0, vh1, vl1;
                cvt_hilo(Vs[(kt8 * 8 + tig) * KLD + dnt * 8 + gid],     vh0, vl0);
                cvt_hilo(Vs[(kt8 * 8 + tig + 4) * KLD + dnt * 8 + gid], vh1, vl1);
                mma8(o[dnt], pa, vh0, vh1);
                mma8(o[dnt], pa, vl0, vl1);
            }
        }

        __syncthreads();   // everyone done with buf (t&1) before refilling it
        if (t + 2 < 16) ATTN_LOAD(t + 2, t & 1);
    }

    // ---- epilogue
    const float inv0 = 1.0f / l0, inv1 = 1.0f / l1;
#pragma unroll
    for (int dnt = 0; dnt < 4; dnt++) {
        const int c = h * HD + dnt * 8 + 2 * tig;
        *(float2*)(outp + ((size_t)b * NTOK + r0) * DIM + c) =
            make_float2(o[dnt][0] * inv0, o[dnt][1] * inv0);
        *(float2*)(outp + ((size_t)b * NTOK + r1) * DIM + c) =
            make_float2(o[dnt][2] * inv1, o[dnt][3] * inv1);
    }
}

// ---------------------------------------------------------------------------
extern "C" void kernel_launch(void* const* d_in, const int* in_sizes, int n_in,
                              void* d_out, int out_size)
{
    (void)in_sizes; (void)n_in; (void)out_size;
    const float* x      = (const float*)d_in[0];
    const float* qkv_w  = (const float*)d_in[1];
    const float* qkv_b  = (const float*)d_in[2];
    const float* proj_w = (const float*)d_in[3];
    const float* proj_b = (const float*)d_in[4];
    const float* temp   = (const float*)d_in[5];
    const float* qe     = (const float*)d_in[6];
    const float* c1w    = (const float*)d_in[7];
    const float* c1b    = (const float*)d_in[8];
    const float* c2w    = (const float*)d_in[9];
    const float* c2b    = (const float*)d_in[10];
    const float* rct    = (const float*)d_in[11];
    const int*   rpi    = (const int*)d_in[12];
    const float* sls    = (const float*)d_in[13];
    float* out = (float*)d_out;

    float *qkv_s, *q_s, *k_s, *v_s, *att_s, *tt_s, *rb_s;
    cudaGetSymbolAddress((void**)&qkv_s, g_qkv);
    cudaGetSymbolAddress((void**)&q_s,   g_q);
    cudaGetSymbolAddress((void**)&k_s,   g_k);
    cudaGetSymbolAddress((void**)&v_s,   g_v);
    cudaGetSymbolAddress((void**)&att_s, g_att);
    cudaGetSymbolAddress((void**)&tt_s,  g_tt);
    cudaGetSymbolAddress((void**)&rb_s,  g_rb);

    cudaFuncSetAttribute(attn_mma, cudaFuncAttributeMaxDynamicSharedMemorySize, ATTN_SMEM);

    // 1. CPB MLP
    cpb_kernel<<<TBL, 512>>>(rct, c1w, c1b, c2w, c2b, tt_s);

    // 2. materialize relative bias [16][1024][1024]
    rb_kernel<<<dim3(NTOK, HEADS), 256>>>(rpi, tt_s, rb_s);

    // 3. qkv projection (3xTF32 tensor cores)
    gemm3t<<<dim3(12, 64), 256>>>(x, qkv_w, qkv_b, qkv_s, B_ * NTOK, 3 * DIM, DIM);

    // 4. split + normalize
    qkv_norm_kernel<<<B_ * NTOK, 512>>>(qkv_s, temp, qe, sls, q_s, k_s, v_s);

    // 5. fused tensor-core attention
    attn_mma<<<dim3(NTOK / 128, HEADS, B_), 256, ATTN_SMEM>>>(q_s, k_s, v_s, rb_s, att_s);

    // 6. output projection (3xTF32 tensor cores)
    gemm3t<<<dim3(4, 64), 256>>>(att_s, proj_w, proj_b, out, B_ * NTOK, DIM, DIM);
}

// round 3
// speedup vs baseline: 2.4360x; 1.6502x over previous
#include <cuda_runtime.h>
#include <cuda_bf16.h>
#include <cstdint>
#include <math.h>
#include <math_constants.h>

#define B_     8
#define NTOK   1024
#define DIM    512
#define HEADS  16
#define HD     32
#define TBL    3969

typedef __nv_bfloat16 bf16;

// ---------------- scratch (device globals; no dynamic allocation) ----------
__device__ float g_qkv[B_ * NTOK * 3 * DIM];                 // fp32 qkv
__device__ bf16  g_xhi[B_ * NTOK * DIM],        g_xlo[B_ * NTOK * DIM];
__device__ bf16  g_wqhi[3 * DIM * DIM],         g_wqlo[3 * DIM * DIM];
__device__ bf16  g_wphi[DIM * DIM],             g_wplo[DIM * DIM];
__device__ bf16  g_Qhi[B_ * HEADS * NTOK * HD], g_Qlo[B_ * HEADS * NTOK * HD];
__device__ bf16  g_Khi[B_ * HEADS * NTOK * HD], g_Klo[B_ * HEADS * NTOK * HD];
__device__ bf16  g_Vhi[B_ * HEADS * NTOK * HD], g_Vlo[B_ * HEADS * NTOK * HD];
__device__ bf16  g_ahi[B_ * NTOK * DIM],        g_alo[B_ * NTOK * DIM];
__device__ bf16  g_rb [HEADS * NTOK * NTOK];                 // 33.5MB bias
__device__ float g_tt [HEADS * TBL];

// ---------------------------------------------------------------------------
// helpers
// ---------------------------------------------------------------------------
__device__ __forceinline__ void mma16(float* d, const unsigned* a, unsigned b0, unsigned b1) {
    asm volatile("mma.sync.aligned.m16n8k16.row.col.f32.bf16.bf16.f32 "
                 "{%0,%1,%2,%3}, {%4,%5,%6,%7}, {%8,%9}, {%0,%1,%2,%3};"
                 : "+f"(d[0]), "+f"(d[1]), "+f"(d[2]), "+f"(d[3])
                 : "r"(a[0]), "r"(a[1]), "r"(a[2]), "r"(a[3]), "r"(b0), "r"(b1));
}
__device__ __forceinline__ void ldsm_x4(unsigned& r0, unsigned& r1, unsigned& r2,
                                        unsigned& r3, unsigned addr) {
    asm volatile("ldmatrix.sync.aligned.m8n8.x4.shared.b16 {%0,%1,%2,%3}, [%4];"
                 : "=r"(r0), "=r"(r1), "=r"(r2), "=r"(r3) : "r"(addr));
}
__device__ __forceinline__ void ldsm_x4t(unsigned& r0, unsigned& r1, unsigned& r2,
                                         unsigned& r3, unsigned addr) {
    asm volatile("ldmatrix.sync.aligned.m8n8.x4.trans.shared.b16 {%0,%1,%2,%3}, [%4];"
                 : "=r"(r0), "=r"(r1), "=r"(r2), "=r"(r3) : "r"(addr));
}
__device__ __forceinline__ void cp16(uint32_t dst, const void* src) {
    asm volatile("cp.async.cg.shared.global [%0], [%1], 16;" :: "r"(dst), "l"(src));
}
#define CP_COMMIT() asm volatile("cp.async.commit_group;" ::: "memory")
#define CP_WAIT1()  asm volatile("cp.async.wait_group 1;" ::: "memory")
#define CP_WAIT0()  asm volatile("cp.async.wait_group 0;" ::: "memory")

__device__ __forceinline__ unsigned packbf(float a, float b) {
    __nv_bfloat162 h = __floats2bfloat162_rn(a, b);
    return *(unsigned*)&h;
}
__device__ __forceinline__ void splitf(float x, bf16& hi, bf16& lo) {
    hi = __float2bfloat16_rn(x);
    lo = __float2bfloat16_rn(x - __bfloat162float(hi));
}

// ---------------------------------------------------------------------------
// Kernel: split fp32 array into bf16 hi/lo planes
// ---------------------------------------------------------------------------
__global__ __launch_bounds__(256)
void split_kernel(const float* __restrict__ in, bf16* __restrict__ hi,
                  bf16* __restrict__ lo, int n)
{
    const int i = (blockIdx.x * 256 + threadIdx.x) * 4;
    if (i >= n) return;
    const float4 v = *(const float4*)(in + i);
    bf16 h0, h1, h2, h3, l0, l1, l2, l3;
    splitf(v.x, h0, l0); splitf(v.y, h1, l1);
    splitf(v.z, h2, l2); splitf(v.w, h3, l3);
    ((uint2*)hi)[i >> 2] = make_uint2(packbf(__bfloat162float(h0), __bfloat162float(h1)),
                                      packbf(__bfloat162float(h2), __bfloat162float(h3)));
    ((uint2*)lo)[i >> 2] = make_uint2(packbf(__bfloat162float(l0), __bfloat162float(l1)),
                                      packbf(__bfloat162float(l2), __bfloat162float(l3)));
}

// ---------------------------------------------------------------------------
// Kernel: continuous position bias MLP
// ---------------------------------------------------------------------------
__global__ __launch_bounds__(512)
void cpb_kernel(const float* __restrict__ tbl, const float* __restrict__ w1,
                const float* __restrict__ b1, const float* __restrict__ w2,
                const float* __restrict__ b2, float* __restrict__ tt)
{
    __shared__ float hid[512];
    const int r = blockIdx.x;
    const int tid = threadIdx.x;
    const float c0 = tbl[r * 2 + 0];
    const float c1 = tbl[r * 2 + 1];
    hid[tid] = fmaxf(fmaf(c0, w1[tid * 2 + 0], fmaf(c1, w1[tid * 2 + 1], b1[tid])), 0.0f);
    __syncthreads();
    const int w = tid >> 5, lane = tid & 31;
    float s = 0.0f;
#pragma unroll
    for (int i = 0; i < 512; i += 32)
        s = fmaf(hid[i + lane], w2[w * 512 + i + lane], s);
#pragma unroll
    for (int msk = 16; msk >= 1; msk >>= 1)
        s += __shfl_xor_sync(0xffffffffu, s, msk);
    if (lane == 0)
        tt[w * TBL + r] = s + b2[w];
}

// ---------------------------------------------------------------------------
// Kernel: materialize rb[h][q][k] = bf16(tt[h][idx[q*1024+k]])
// ---------------------------------------------------------------------------
__global__ __launch_bounds__(256)
void rb_kernel(const int* __restrict__ idx, const float* __restrict__ tt,
               bf16* __restrict__ rb)
{
    const int q = blockIdx.x, h = blockIdx.y;
    const int k = threadIdx.x * 4;
    const int4 id = *(const int4*)(idx + q * NTOK + k);
    const float* tth = tt + h * TBL;
    ((uint2*)rb)[(((size_t)h * NTOK + q) * NTOK + k) >> 2] =
        make_uint2(packbf(tth[id.x], tth[id.y]), packbf(tth[id.z], tth[id.w]));
}

// ---------------------------------------------------------------------------
// Kernel: 3xBF16 split NT-GEMM. C = A[M][K] @ B[N][K]^T + bias[N]
// 128x128 tile, k-step 32, 256 threads / 8 warps (2m x 4n), cp.async 2-stage.
// smem per buffer: Ahi(10240B) Alo Bhi Blo -> 40960B; x2 buffers = 80KB.
// ---------------------------------------------------------------------------
#define GBUF 40960
#define GROW 40   // bf16 row stride (80B: 16B-aligned chunks, conflict-free LDSM)

__global__ __launch_bounds__(256, 2)
void gemm_bs(const bf16* __restrict__ Ahi, const bf16* __restrict__ Alo,
             const bf16* __restrict__ Bhi, const bf16* __restrict__ Blo,
             const float* __restrict__ bias, float* __restrict__ C,
             int M, int N, int K)
{
    extern __shared__ __align__(16) char smraw[];
    const uint32_t smb = (uint32_t)__cvta_generic_to_shared(smraw);

    const int tid = threadIdx.x;
    const int w = tid >> 5, lane = tid & 31;
    const int gid = lane >> 2, tig = lane & 3;
    const int wm = w >> 2, wn = w & 3;
    const int row0 = blockIdx.y * 128, col0 = blockIdx.x * 128;
    const int NS = K / 32;

    // ldmatrix lane address patterns (byte offsets within a plane)
    const int rowA = (lane & 7) | (lane & 8);
    const uint32_t aoff = (uint32_t)(rowA * GROW + ((lane & 16) >> 1)) * 2;
    const int rowB = (lane & 7) | ((lane & 16) >> 1);
    const uint32_t boff = (uint32_t)(rowB * GROW + (lane & 8)) * 2;

    float acc[4][4][4];
#pragma unroll
    for (int i = 0; i < 4; i++)
#pragma unroll
        for (int j = 0; j < 4; j++)
#pragma unroll
            for (int q = 0; q < 4; q++) acc[i][j][q] = 0.0f;

#define GEMM_LOAD(s, buf)                                                          \
    {                                                                              \
        const int k0_ = (s) * 32;                                                  \
        _Pragma("unroll")                                                          \
        for (int i_ = 0; i_ < 2; i_++) {                                           \
            const int slot_ = tid + i_ * 256;                                      \
            const int r_ = slot_ >> 2, q_ = slot_ & 3;                             \
            const uint32_t d_ = smb + (buf) * GBUF + (uint32_t)(r_ * 80 + q_ * 16);\
            const size_t ga_ = (size_t)(row0 + r_) * K + k0_ + q_ * 8;             \
            const size_t gb_ = (size_t)(col0 + r_) * K + k0_ + q_ * 8;             \
            cp16(d_,         Ahi + ga_);                                           \
            cp16(d_ + 10240, Alo + ga_);                                           \
            cp16(d_ + 20480, Bhi + gb_);                                           \
            cp16(d_ + 30720, Blo + gb_);                                           \
        }                                                                          \
        CP_COMMIT();                                                               \
    }

    GEMM_LOAD(0, 0);
    GEMM_LOAD(1, 1);

    for (int s = 0; s < NS; s++) {
        if (s < NS - 1) { CP_WAIT1(); } else { CP_WAIT0(); }
        __syncthreads();
        const uint32_t base = smb + (s & 1) * GBUF;
#pragma unroll
        for (int kt = 0; kt < 2; kt++) {
            unsigned bh[4][2], bl[4][2];
#pragma unroll
            for (int ntp = 0; ntp < 2; ntp++) {
                const uint32_t ba = base + 20480 + boff
                                  + (uint32_t)((wn * 32 + ntp * 16) * 80 + kt * 32);
                ldsm_x4(bh[2*ntp][0], bh[2*ntp][1], bh[2*ntp+1][0], bh[2*ntp+1][1], ba);
                ldsm_x4(bl[2*ntp][0], bl[2*ntp][1], bl[2*ntp+1][0], bl[2*ntp+1][1], ba + 10240);
            }
#pragma unroll
            for (int mt = 0; mt < 4; mt++) {
                const uint32_t aa = base + aoff
                                  + (uint32_t)((wm * 64 + mt * 16) * 80 + kt * 32);
                unsigned ah[4], al[4];
                ldsm_x4(ah[0], ah[1], ah[2], ah[3], aa);
                ldsm_x4(al[0], al[1], al[2], al[3], aa + 10240);
#pragma unroll
                for (int nt = 0; nt < 4; nt++) {
                    mma16(acc[mt][nt], ah, bh[nt][0], bh[nt][1]);
                    mma16(acc[mt][nt], al, bh[nt][0], bh[nt][1]);
                    mma16(acc[mt][nt], ah, bl[nt][0], bl[nt][1]);
                }
            }
        }
        __syncthreads();
        if (s + 2 < NS) GEMM_LOAD(s + 2, s & 1);
    }

#pragma unroll
    for (int mt = 0; mt < 4; mt++) {
        const int ra = row0 + wm * 64 + mt * 16 + gid;
#pragma unroll
        for (int nt = 0; nt < 4; nt++) {
            const int c = col0 + wn * 32 + nt * 8 + 2 * tig;
            const float bb0 = bias[c], bb1 = bias[c + 1];
            *(float2*)(C + (size_t)ra * N + c) =
                make_float2(acc[mt][nt][0] + bb0, acc[mt][nt][1] + bb1);
            *(float2*)(C + (size_t)(ra + 8) * N + c) =
                make_float2(acc[mt][nt][2] + bb0, acc[mt][nt][3] + bb1);
        }
    }
}

// ---------------------------------------------------------------------------
// Kernel: split qkv + l2norm + scale; outputs bf16 hi/lo planes [b][h][n][32]
// ---------------------------------------------------------------------------
__global__ __launch_bounds__(512)
void qkv_norm_kernel(const float* __restrict__ raw, const float* __restrict__ temp,
                     const float* __restrict__ qe, const float* __restrict__ sls,
                     bf16* __restrict__ Qhi, bf16* __restrict__ Qlo,
                     bf16* __restrict__ Khi, bf16* __restrict__ Klo,
                     bf16* __restrict__ Vhi, bf16* __restrict__ Vlo)
{
    const int row = blockIdx.x;
    const int b = row >> 10, n = row & 1023;
    const int tid = threadIdx.x;
    const int h = tid >> 5, lane = tid & 31;
    const size_t base = (size_t)row * (3 * DIM);

    const float qv = raw[base + tid];
    const float kv = raw[base + DIM + tid];
    const float vv = raw[base + 2 * DIM + tid];

    float sq = qv * qv;
#pragma unroll
    for (int msk = 16; msk >= 1; msk >>= 1) sq += __shfl_xor_sync(0xffffffffu, sq, msk);
    float qn = qv / fmaxf(sqrtf(sq), 1e-12f);
    const float scale = log1pf(expf(temp[h])) * sls[0];
    qn = (qn + qe[h * HD + lane]) * scale;

    float sk = kv * kv;
#pragma unroll
    for (int msk = 16; msk >= 1; msk >>= 1) sk += __shfl_xor_sync(0xffffffffu, sk, msk);
    const float kn = kv / fmaxf(sqrtf(sk), 1e-12f);

    const size_t o = ((((size_t)b * HEADS) + h) * NTOK + n) * HD + lane;
    bf16 hi, lo;
    splitf(qn, hi, lo); Qhi[o] = hi; Qlo[o] = lo;
    splitf(kn, hi, lo); Khi[o] = hi; Klo[o] = lo;
    splitf(vv, hi, lo); Vhi[o] = hi; Vlo[o] = lo;
}

// ---------------------------------------------------------------------------
// Kernel: bf16-split tensor-core flash attention.
// Block = (b, h, 128-query tile), 8 warps x 16 q-rows. Key tiles of 64.
// smem: Khi/Klo/Vhi/Vlo 64x40 bf16 (single-buffered, 20KB) + P hi/lo per warp.
// ---------------------------------------------------------------------------
#define KROW 40
#define KPS  (64 * KROW * 2)        // 5120B per plane
#define PWU  36                     // P row stride in uints (144B)
#define PBASE (4 * KPS)             // 20480
#define PWSZ (16 * PWU * 4)         // 2304B per plane
#define ATTN_SMEM (PBASE + 8 * 2 * PWSZ)   // 57344B

__global__ __launch_bounds__(256, 2)
void attn_mma(const bf16* __restrict__ Qhi_, const bf16* __restrict__ Qlo_,
              const bf16* __restrict__ Khi_, const bf16* __restrict__ Klo_,
              const bf16* __restrict__ Vhi_, const bf16* __restrict__ Vlo_,
              const bf16* __restrict__ rb, bf16* __restrict__ outhi,
              bf16* __restrict__ outlo)
{
    extern __shared__ __align__(16) char smraw[];
    const uint32_t smb = (uint32_t)__cvta_generic_to_shared(smraw);

    const int tid = threadIdx.x;
    const int w = tid >> 5, lane = tid & 31;
    const int gid = lane >> 2, tig = lane & 3;
    const int q0 = blockIdx.x * 128, h = blockIdx.y, b = blockIdx.z;
    const size_t bh = ((size_t)b * HEADS + h) * NTOK * HD;
    const bf16* Khg = Khi_ + bh;
    const bf16* Klg = Klo_ + bh;
    const bf16* Vhg = Vhi_ + bh;
    const bf16* Vlg = Vlo_ + bh;
    const bf16* rbh = rb + (size_t)h * NTOK * NTOK;
    const int r0 = q0 + w * 16 + gid;
    const int r1 = r0 + 8;

    // ldmatrix lane patterns (byte offsets)
    const uint32_t koff = (uint32_t)((((lane & 7) | ((lane & 16) >> 1)) * KROW + (lane & 8)) * 2);
    const uint32_t voff = (uint32_t)((((lane & 7) | (lane & 8)) * KROW + ((lane & 16) >> 1)) * 2);
    const uint32_t poff = (uint32_t)((((lane & 7) | (lane & 8)) * PWU + ((lane & 16) >> 2)) * 4);
    const uint32_t pwh = smb + PBASE + (uint32_t)w * (2 * PWSZ);
    const uint32_t pwl = pwh + PWSZ;
    unsigned* PwH = (unsigned*)(smraw + PBASE + w * (2 * PWSZ));
    unsigned* PwL = (unsigned*)(smraw + PBASE + w * (2 * PWSZ) + PWSZ);

    // Q fragments from global (hi/lo), kt = d/16
    unsigned qh[2][4], ql[2][4];
#pragma unroll
    for (int kt = 0; kt < 2; kt++) {
        const int d0 = kt * 16 + 2 * tig;
        qh[kt][0] = *(const unsigned*)(Qhi_ + bh + (size_t)r0 * HD + d0);
        qh[kt][1] = *(const unsigned*)(Qhi_ + bh + (size_t)r1 * HD + d0);
        qh[kt][2] = *(const unsigned*)(Qhi_ + bh + (size_t)r0 * HD + d0 + 8);
        qh[kt][3] = *(const unsigned*)(Qhi_ + bh + (size_t)r1 * HD + d0 + 8);
        ql[kt][0] = *(const unsigned*)(Qlo_ + bh + (size_t)r0 * HD + d0);
        ql[kt][1] = *(const unsigned*)(Qlo_ + bh + (size_t)r1 * HD + d0);
        ql[kt][2] = *(const unsigned*)(Qlo_ + bh + (size_t)r0 * HD + d0 + 8);
        ql[kt][3] = *(const unsigned*)(Qlo_ + bh + (size_t)r1 * HD + d0 + 8);
    }

    float o[4][4];
#pragma unroll
    for (int i = 0; i < 4; i++)
#pragma unroll
        for (int j = 0; j < 4; j++) o[i][j] = 0.0f;
    float m0 = -CUDART_INF_F, m1 = -CUDART_INF_F, l0 = 0.0f, l1 = 0.0f;

    for (int t = 0; t < 16; t++) {
        const int key0 = t * 64;
        __syncthreads();   // everyone done reading previous tile's smem
        // async load K/V hi/lo tiles: 256 chunks of 16B per plane, 1 per thread
        {
            const int r_ = tid >> 2, q_ = tid & 3;
            const uint32_t d_ = smb + (uint32_t)(r_ * 80 + q_ * 16);
            const size_t g_ = (size_t)(key0 + r_) * HD + q_ * 8;
            cp16(d_,           Khg + g_);
            cp16(d_ + KPS,     Klg + g_);
            cp16(d_ + 2 * KPS, Vhg + g_);
            cp16(d_ + 3 * KPS, Vlg + g_);
            CP_COMMIT();
        }

        // S accumulators initialized with gathered bias (overlaps cp.async)
        float s[8][4];
#pragma unroll
        for (int nt = 0; nt < 8; nt++) {
            const float2 u0 = __bfloat1622float2(
                *(const __nv_bfloat162*)(rbh + ((size_t)r0 << 10) + key0 + nt * 8 + 2 * tig));
            const float2 u1 = __bfloat1622float2(
                *(const __nv_bfloat162*)(rbh + ((size_t)r1 << 10) + key0 + nt * 8 + 2 * tig));
            s[nt][0] = u0.x; s[nt][1] = u0.y; s[nt][2] = u1.x; s[nt][3] = u1.y;
        }

        CP_WAIT0();
        __syncthreads();

        // ---- S += Q K^T (3xBF16)
#pragma unroll
        for (int kt = 0; kt < 2; kt++) {
#pragma unroll
            for (int ntp = 0; ntp < 4; ntp++) {
                const uint32_t ka = smb + koff + (uint32_t)(ntp * 1280 + kt * 32);
                unsigned kh0, kh1, kh2, kh3, kl0, kl1, kl2, kl3;
                ldsm_x4(kh0, kh1, kh2, kh3, ka);
                ldsm_x4(kl0, kl1, kl2, kl3, ka + KPS);
                mma16(s[2*ntp],   qh[kt], kh0, kh1);
                mma16(s[2*ntp],   ql[kt], kh0, kh1);
                mma16(s[2*ntp],   qh[kt], kl0, kl1);
                mma16(s[2*ntp+1], qh[kt], kh2, kh3);
                mma16(s[2*ntp+1], ql[kt], kh2, kh3);
                mma16(s[2*ntp+1], qh[kt], kl2, kl3);
            }
        }

        // ---- online softmax
        float mx0 = s[0][0], mx1 = s[0][2];
#pragma unroll
        for (int nt = 0; nt < 8; nt++) {
            mx0 = fmaxf(mx0, fmaxf(s[nt][0], s[nt][1]));
            mx1 = fmaxf(mx1, fmaxf(s[nt][2], s[nt][3]));
        }
        mx0 = fmaxf(mx0, __shfl_xor_sync(0xffffffffu, mx0, 1));
        mx0 = fmaxf(mx0, __shfl_xor_sync(0xffffffffu, mx0, 2));
        mx1 = fmaxf(mx1, __shfl_xor_sync(0xffffffffu, mx1, 1));
        mx1 = fmaxf(mx1, __shfl_xor_sync(0xffffffffu, mx1, 2));
        const float mn0 = fmaxf(m0, mx0), mn1 = fmaxf(m1, mx1);
        const float cf0 = __expf(m0 - mn0), cf1 = __expf(m1 - mn1);
        float sum0 = 0.0f, sum1 = 0.0f;
#pragma unroll
        for (int nt = 0; nt < 8; nt++) {
            s[nt][0] = __expf(s[nt][0] - mn0);
            s[nt][1] = __expf(s[nt][1] - mn0);
            s[nt][2] = __expf(s[nt][2] - mn1);
            s[nt][3] = __expf(s[nt][3] - mn1);
            sum0 += s[nt][0] + s[nt][1];
            sum1 += s[nt][2] + s[nt][3];
        }
        sum0 += __shfl_xor_sync(0xffffffffu, sum0, 1);
        sum0 += __shfl_xor_sync(0xffffffffu, sum0, 2);
        sum1 += __shfl_xor_sync(0xffffffffu, sum1, 1);
        sum1 += __shfl_xor_sync(0xffffffffu, sum1, 2);
        l0 = l0 * cf0 + sum0;
        l1 = l1 * cf1 + sum1;
        m0 = mn0; m1 = mn1;
#pragma unroll
        for (int dnt = 0; dnt < 4; dnt++) {
            o[dnt][0] *= cf0; o[dnt][1] *= cf0;
            o[dnt][2] *= cf1; o[dnt][3] *= cf1;
        }

        // ---- stage P hi/lo to per-warp smem as packed bf16x2
#pragma unroll
        for (int nt = 0; nt < 8; nt++) {
            const int cu = nt * 4 + tig;
            unsigned ph, pl;
            {
                float hx = __bfloat162float(__float2bfloat16_rn(s[nt][0]));
                float hy = __bfloat162float(__float2bfloat16_rn(s[nt][1]));
                ph = packbf(s[nt][0], s[nt][1]);   // rn of each
                pl = packbf(s[nt][0] - hx, s[nt][1] - hy);
            }
            PwH[gid * PWU + cu] = ph;
            PwL[gid * PWU + cu] = pl;
            {
                float hx = __bfloat162float(__float2bfloat16_rn(s[nt][2]));
                float hy = __bfloat162float(__float2bfloat16_rn(s[nt][3]));
                ph = packbf(s[nt][2], s[nt][3]);
                pl = packbf(s[nt][2] - hx, s[nt][3] - hy);
            }
            PwH[(gid + 8) * PWU + cu] = ph;
            PwL[(gid + 8) * PWU + cu] = pl;
        }
        __syncwarp();

        // ---- O += P V (3xBF16: PhVh + PlVh + PhVl)
#pragma unroll
        for (int kt = 0; kt < 4; kt++) {
            unsigned ph[4], pl[4];
            ldsm_x4(ph[0], ph[1], ph[2], ph[3], pwh + poff + kt * 32);
            ldsm_x4(pl[0], pl[1], pl[2], pl[3], pwl + poff + kt * 32);
#pragma unroll
            for (int ntp = 0; ntp < 2; ntp++) {
                const uint32_t va = smb + 2 * KPS + voff + (uint32_t)(kt * 1280 + ntp * 32);
                unsigned vh0, vh1, vh2, vh3, vl0, vl1, vl2, vl3;
                ldsm_x4t(vh0, vh1, vh2, vh3, va);
                ldsm_x4t(vl0, vl1, vl2, vl3, va + KPS);
                mma16(o[2*ntp],   ph, vh0, vh1);
                mma16(o[2*ntp],   pl, vh0, vh1);
                mma16(o[2*ntp],   ph, vl0, vl1);
                mma16(o[2*ntp+1], ph, vh2, vh3);
                mma16(o[2*ntp+1], pl, vh2, vh3);
                mma16(o[2*ntp+1], ph, vl2, vl3);
            }
        }
    }

    // ---- epilogue: normalize, split hi/lo, write packed pairs
    const float inv0 = 1.0f / l0, inv1 = 1.0f / l1;
#pragma unroll
    for (int dnt = 0; dnt < 4; dnt++) {
        const int c = h * HD + dnt * 8 + 2 * tig;
        {
            const float v0 = o[dnt][0] * inv0, v1 = o[dnt][1] * inv0;
            const float h0 = __bfloat162float(__float2bfloat16_rn(v0));
            const float h1 = __bfloat162float(__float2bfloat16_rn(v1));
            const size_t u = ((size_t)(((size_t)b << 10) + r0) * DIM + c) >> 1;
            ((unsigned*)outhi)[u] = packbf(v0, v1);
            ((unsigned*)outlo)[u] = packbf(v0 - h0, v1 - h1);
        }
        {
            const float v0 = o[dnt][2] * inv1, v1 = o[dnt][3] * inv1;
            const float h0 = __bfloat162float(__float2bfloat16_rn(v0));
            const float h1 = __bfloat162float(__float2bfloat16_rn(v1));
            const size_t u = ((size_t)(((size_t)b << 10) + r1) * DIM + c) >> 1;
            ((unsigned*)outhi)[u] = packbf(v0, v1);
            ((unsigned*)outlo)[u] = packbf(v0 - h0, v1 - h1);
        }
    }
}

// ---------------------------------------------------------------------------
extern "C" void kernel_launch(void* const* d_in, const int* in_sizes, int n_in,
                              void* d_out, int out_size)
{
    (void)in_sizes; (void)n_in; (void)out_size;
    const float* x      = (const float*)d_in[0];
    const float* qkv_w  = (const float*)d_in[1];
    const float* qkv_b  = (const float*)d_in[2];
    const float* proj_w = (const float*)d_in[3];
    const float* proj_b = (const float*)d_in[4];
    const float* temp   = (const float*)d_in[5];
    const float* qe     = (const float*)d_in[6];
    const float* c1w    = (const float*)d_in[7];
    const float* c1b    = (const float*)d_in[8];
    const float* c2w    = (const float*)d_in[9];
    const float* c2b    = (const float*)d_in[10];
    const float* rct    = (const float*)d_in[11];
    const int*   rpi    = (const int*)d_in[12];
    const float* sls    = (const float*)d_in[13];
    float* out = (float*)d_out;

    float *qkv_s, *tt_s;
    bf16 *xhi, *xlo, *wqhi, *wqlo, *wphi, *wplo;
    bf16 *Qhi, *Qlo, *Khi, *Klo, *Vhi, *Vlo, *ahi, *alo, *rb_s;
    cudaGetSymbolAddress((void**)&qkv_s, g_qkv);
    cudaGetSymbolAddress((void**)&tt_s,  g_tt);
    cudaGetSymbolAddress((void**)&xhi,  g_xhi);  cudaGetSymbolAddress((void**)&xlo,  g_xlo);
    cudaGetSymbolAddress((void**)&wqhi, g_wqhi); cudaGetSymbolAddress((void**)&wqlo, g_wqlo);
    cudaGetSymbolAddress((void**)&wphi, g_wphi); cudaGetSymbolAddress((void**)&wplo, g_wplo);
    cudaGetSymbolAddress((void**)&Qhi,  g_Qhi);  cudaGetSymbolAddress((void**)&Qlo,  g_Qlo);
    cudaGetSymbolAddress((void**)&Khi,  g_Khi);  cudaGetSymbolAddress((void**)&Klo,  g_Klo);
    cudaGetSymbolAddress((void**)&Vhi,  g_Vhi);  cudaGetSymbolAddress((void**)&Vlo,  g_Vlo);
    cudaGetSymbolAddress((void**)&ahi,  g_ahi);  cudaGetSymbolAddress((void**)&alo,  g_alo);
    cudaGetSymbolAddress((void**)&rb_s, g_rb);

    cudaFuncSetAttribute(attn_mma, cudaFuncAttributeMaxDynamicSharedMemorySize, ATTN_SMEM);
    cudaFuncSetAttribute(gemm_bs, cudaFuncAttributeMaxDynamicSharedMemorySize, 2 * GBUF);

    // 1. CPB MLP + bias materialization
    cpb_kernel<<<TBL, 512>>>(rct, c1w, c1b, c2w, c2b, tt_s);
    rb_kernel<<<dim3(NTOK, HEADS), 256>>>(rpi, tt_s, rb_s);

    // 2. split x and weights into bf16 hi/lo planes
    split_kernel<<<(B_ * NTOK * DIM / 4 + 255) / 256, 256>>>(x, xhi, xlo, B_ * NTOK * DIM);
    split_kernel<<<(3 * DIM * DIM / 4 + 255) / 256, 256>>>(qkv_w, wqhi, wqlo, 3 * DIM * DIM);
    split_kernel<<<(DIM * DIM / 4 + 255) / 256, 256>>>(proj_w, wphi, wplo, DIM * DIM);

    // 3. qkv projection (3xBF16 tensor cores)
    gemm_bs<<<dim3(12, 64), 256, 2 * GBUF>>>(xhi, xlo, wqhi, wqlo, qkv_b, qkv_s,
                                             B_ * NTOK, 3 * DIM, DIM);

    // 4. split + normalize -> bf16 hi/lo planes
    qkv_norm_kernel<<<B_ * NTOK, 512>>>(qkv_s, temp, qe, sls,
                                        Qhi, Qlo, Khi, Klo, Vhi, Vlo);

    // 5. fused tensor-core attention -> bf16 hi/lo planes
    attn_mma<<<dim3(NTOK / 128, HEADS, B_), 256, ATTN_SMEM>>>(
        Qhi, Qlo, Khi, Klo, Vhi, Vlo, rb_s, ahi, alo);

    // 6. output projection (3xBF16 tensor cores) -> fp32 out
    gemm_bs<<<dim3(4, 64), 256, 2 * GBUF>>>(ahi, alo, wphi, wplo, proj_b, out,
                                            B_ * NTOK, DIM, DIM);
}

// round 4
// speedup vs baseline: 2.6123x; 1.0724x over previous
#include <cuda_runtime.h>
#include <cuda_bf16.h>
#include <cstdint>
#include <math.h>
#include <math_constants.h>

#define B_     8
#define NTOK   1024
#define DIM    512
#define HEADS  16
#define HD     32
#define TBL    3969
#define LOG2E  1.4426950408889634f

typedef __nv_bfloat16 bf16;

// ---------------- scratch (device globals; no dynamic allocation) ----------
__device__ bf16  g_xhi[B_ * NTOK * DIM],        g_xlo[B_ * NTOK * DIM];
__device__ bf16  g_wqhi[3 * DIM * DIM],         g_wqlo[3 * DIM * DIM];
__device__ bf16  g_wphi[DIM * DIM],             g_wplo[DIM * DIM];
__device__ bf16  g_Qhi[B_ * HEADS * NTOK * HD], g_Qlo[B_ * HEADS * NTOK * HD];
__device__ bf16  g_Khi[B_ * HEADS * NTOK * HD], g_Klo[B_ * HEADS * NTOK * HD];
__device__ bf16  g_Vhi[B_ * HEADS * NTOK * HD], g_Vlo[B_ * HEADS * NTOK * HD];
__device__ bf16  g_ahi[B_ * NTOK * DIM],        g_alo[B_ * NTOK * DIM];
__device__ bf16  g_rb [HEADS * NTOK * NTOK];                 // bias * log2e
__device__ float g_tt [HEADS * TBL];

// ---------------------------------------------------------------------------
// helpers
// ---------------------------------------------------------------------------
__device__ __forceinline__ void mma16(float* d, const unsigned* a, unsigned b0, unsigned b1) {
    asm volatile("mma.sync.aligned.m16n8k16.row.col.f32.bf16.bf16.f32 "
                 "{%0,%1,%2,%3}, {%4,%5,%6,%7}, {%8,%9}, {%0,%1,%2,%3};"
                 : "+f"(d[0]), "+f"(d[1]), "+f"(d[2]), "+f"(d[3])
                 : "r"(a[0]), "r"(a[1]), "r"(a[2]), "r"(a[3]), "r"(b0), "r"(b1));
}
__device__ __forceinline__ void ldsm_x4(unsigned& r0, unsigned& r1, unsigned& r2,
                                        unsigned& r3, unsigned addr) {
    asm volatile("ldmatrix.sync.aligned.m8n8.x4.shared.b16 {%0,%1,%2,%3}, [%4];"
                 : "=r"(r0), "=r"(r1), "=r"(r2), "=r"(r3) : "r"(addr));
}
__device__ __forceinline__ void ldsm_x4t(unsigned& r0, unsigned& r1, unsigned& r2,
                                         unsigned& r3, unsigned addr) {
    asm volatile("ldmatrix.sync.aligned.m8n8.x4.trans.shared.b16 {%0,%1,%2,%3}, [%4];"
                 : "=r"(r0), "=r"(r1), "=r"(r2), "=r"(r3) : "r"(addr));
}
__device__ __forceinline__ void cp16(uint32_t dst, const void* src) {
    asm volatile("cp.async.cg.shared.global [%0], [%1], 16;" :: "r"(dst), "l"(src));
}
#define CP_COMMIT() asm volatile("cp.async.commit_group;" ::: "memory")
#define CP_WAIT1()  asm volatile("cp.async.wait_group 1;" ::: "memory")
#define CP_WAIT0()  asm volatile("cp.async.wait_group 0;" ::: "memory")

__device__ __forceinline__ unsigned packbf(float a, float b) {
    __nv_bfloat162 h = __floats2bfloat162_rn(a, b);
    return *(unsigned*)&h;
}
__device__ __forceinline__ void splitf(float x, bf16& hi, bf16& lo) {
    hi = __float2bfloat16_rn(x);
    lo = __float2bfloat16_rn(x - __bfloat162float(hi));
}
__device__ __forceinline__ float ex2(float x) {
    float r;
    asm("ex2.approx.ftz.f32 %0, %1;" : "=f"(r) : "f"(x));
    return r;
}

// ---------------------------------------------------------------------------
// Kernel: split fp32 array into bf16 hi/lo planes
// ---------------------------------------------------------------------------
__global__ __launch_bounds__(256)
void split_kernel(const float* __restrict__ in, bf16* __restrict__ hi,
                  bf16* __restrict__ lo, int n)
{
    const int i = (blockIdx.x * 256 + threadIdx.x) * 4;
    if (i >= n) return;
    const float4 v = *(const float4*)(in + i);
    bf16 h0, h1, h2, h3, l0, l1, l2, l3;
    splitf(v.x, h0, l0); splitf(v.y, h1, l1);
    splitf(v.z, h2, l2); splitf(v.w, h3, l3);
    ((uint2*)hi)[i >> 2] = make_uint2(packbf(__bfloat162float(h0), __bfloat162float(h1)),
                                      packbf(__bfloat162float(h2), __bfloat162float(h3)));
    ((uint2*)lo)[i >> 2] = make_uint2(packbf(__bfloat162float(l0), __bfloat162float(l1)),
                                      packbf(__bfloat162float(l2), __bfloat162float(l3)));
}

// ---------------------------------------------------------------------------
// Kernel: continuous position bias MLP
// ---------------------------------------------------------------------------
__global__ __launch_bounds__(512)
void cpb_kernel(const float* __restrict__ tbl, const float* __restrict__ w1,
                const float* __restrict__ b1, const float* __restrict__ w2,
                const float* __restrict__ b2, float* __restrict__ tt)
{
    __shared__ float hid[512];
    const int r = blockIdx.x;
    const int tid = threadIdx.x;
    const float c0 = tbl[r * 2 + 0];
    const float c1 = tbl[r * 2 + 1];
    hid[tid] = fmaxf(fmaf(c0, w1[tid * 2 + 0], fmaf(c1, w1[tid * 2 + 1], b1[tid])), 0.0f);
    __syncthreads();
    const int w = tid >> 5, lane = tid & 31;
    float s = 0.0f;
#pragma unroll
    for (int i = 0; i < 512; i += 32)
        s = fmaf(hid[i + lane], w2[w * 512 + i + lane], s);
#pragma unroll
    for (int msk = 16; msk >= 1; msk >>= 1)
        s += __shfl_xor_sync(0xffffffffu, s, msk);
    if (lane == 0)
        tt[w * TBL + r] = s + b2[w];
}

// ---------------------------------------------------------------------------
// Kernel: materialize rb[h][q][k] = bf16(log2e * tt[h][idx[q*1024+k]])
// ---------------------------------------------------------------------------
__global__ __launch_bounds__(256)
void rb_kernel(const int* __restrict__ idx, const float* __restrict__ tt,
               bf16* __restrict__ rb)
{
    const int q = blockIdx.x, h = blockIdx.y;
    const int k = threadIdx.x * 4;
    const int4 id = *(const int4*)(idx + q * NTOK + k);
    const float* tth = tt + h * TBL;
    ((uint2*)rb)[(((size_t)h * NTOK + q) * NTOK + k) >> 2] =
        make_uint2(packbf(tth[id.x] * LOG2E, tth[id.y] * LOG2E),
                   packbf(tth[id.z] * LOG2E, tth[id.w] * LOG2E));
}

// ---------------------------------------------------------------------------
// Kernel: 3xBF16 split NT-GEMM. 128x128 tile, k-step 32, 8 warps (2m x 4n).
// MODE 0: C fp32 = A B^T + bias.
// MODE 1: fused qkv epilogue — per-head l2norm (+query-embed, temp scale,
//         log2e fold for q), split into bf16 hi/lo planes [b][h][n][32].
// ---------------------------------------------------------------------------
#define GBUF 40960
#define GROW 40

template<int MODE>
__global__ __launch_bounds__(256, 2)
void gemm_bs(const bf16* __restrict__ Ahi, const bf16* __restrict__ Alo,
             const bf16* __restrict__ Bhi, const bf16* __restrict__ Blo,
             const float* __restrict__ bias, float* __restrict__ C,
             int M, int N, int K,
             const float* __restrict__ temp, const float* __restrict__ qe,
             const float* __restrict__ sls,
             bf16* __restrict__ Qhi, bf16* __restrict__ Qlo,
             bf16* __restrict__ Khi, bf16* __restrict__ Klo,
             bf16* __restrict__ Vhi, bf16* __restrict__ Vlo)
{
    extern __shared__ __align__(16) char smraw[];
    const uint32_t smb = (uint32_t)__cvta_generic_to_shared(smraw);

    const int tid = threadIdx.x;
    const int w = tid >> 5, lane = tid & 31;
    const int gid = lane >> 2, tig = lane & 3;
    const int wm = w >> 2, wn = w & 3;
    const int row0 = blockIdx.y * 128, col0 = blockIdx.x * 128;
    const int NS = K / 32;

    const int rowA = (lane & 7) | (lane & 8);
    const uint32_t aoff = (uint32_t)(rowA * GROW + ((lane & 16) >> 1)) * 2;
    const int rowB = (lane & 7) | ((lane & 16) >> 1);
    const uint32_t boff = (uint32_t)(rowB * GROW + (lane & 8)) * 2;

    float acc[4][4][4];
#pragma unroll
    for (int i = 0; i < 4; i++)
#pragma unroll
        for (int j = 0; j < 4; j++)
#pragma unroll
            for (int q = 0; q < 4; q++) acc[i][j][q] = 0.0f;

#define GEMM_LOAD(s, buf)                                                          \
    {                                                                              \
        const int k0_ = (s) * 32;                                                  \
        _Pragma("unroll")                                                          \
        for (int i_ = 0; i_ < 2; i_++) {                                           \
            const int slot_ = tid + i_ * 256;                                      \
            const int r_ = slot_ >> 2, q_ = slot_ & 3;                             \
            const uint32_t d_ = smb + (buf) * GBUF + (uint32_t)(r_ * 80 + q_ * 16);\
            const size_t ga_ = (size_t)(row0 + r_) * K + k0_ + q_ * 8;             \
            const size_t gb_ = (size_t)(col0 + r_) * K + k0_ + q_ * 8;             \
            cp16(d_,         Ahi + ga_);                                           \
            cp16(d_ + 10240, Alo + ga_);                                           \
            cp16(d_ + 20480, Bhi + gb_);                                           \
            cp16(d_ + 30720, Blo + gb_);                                           \
        }                                                                          \
        CP_COMMIT();                                                               \
    }

    GEMM_LOAD(0, 0);
    GEMM_LOAD(1, 1);

    for (int s = 0; s < NS; s++) {
        if (s < NS - 1) { CP_WAIT1(); } else { CP_WAIT0(); }
        __syncthreads();
        const uint32_t base = smb + (s & 1) * GBUF;
#pragma unroll
        for (int kt = 0; kt < 2; kt++) {
            unsigned bh[4][2], bl[4][2];
#pragma unroll
            for (int ntp = 0; ntp < 2; ntp++) {
                const uint32_t ba = base + 20480 + boff
                                  + (uint32_t)((wn * 32 + ntp * 16) * 80 + kt * 32);
                ldsm_x4(bh[2*ntp][0], bh[2*ntp][1], bh[2*ntp+1][0], bh[2*ntp+1][1], ba);
                ldsm_x4(bl[2*ntp][0], bl[2*ntp][1], bl[2*ntp+1][0], bl[2*ntp+1][1], ba + 10240);
            }
#pragma unroll
            for (int mt = 0; mt < 4; mt++) {
                const uint32_t aa = base + aoff
                                  + (uint32_t)((wm * 64 + mt * 16) * 80 + kt * 32);
                unsigned ah[4], al[4];
                ldsm_x4(ah[0], ah[1], ah[2], ah[3], aa);
                ldsm_x4(al[0], al[1], al[2], al[3], aa + 10240);
#pragma unroll
                for (int nt = 0; nt < 4; nt++) {
                    mma16(acc[mt][nt], ah, bh[nt][0], bh[nt][1]);
                    mma16(acc[mt][nt], al, bh[nt][0], bh[nt][1]);
                    mma16(acc[mt][nt], ah, bl[nt][0], bl[nt][1]);
                }
            }
        }
        __syncthreads();
        if (s + 2 < NS) GEMM_LOAD(s + 2, s & 1);
    }

    if (MODE == 0) {
#pragma unroll
        for (int mt = 0; mt < 4; mt++) {
            const int ra = row0 + wm * 64 + mt * 16 + gid;
#pragma unroll
            for (int nt = 0; nt < 4; nt++) {
                const int c = col0 + wn * 32 + nt * 8 + 2 * tig;
                const float bb0 = bias[c], bb1 = bias[c + 1];
                *(float2*)(C + (size_t)ra * N + c) =
                    make_float2(acc[mt][nt][0] + bb0, acc[mt][nt][1] + bb1);
                *(float2*)(C + (size_t)(ra + 8) * N + c) =
                    make_float2(acc[mt][nt][2] + bb0, acc[mt][nt][3] + bb1);
            }
        }
    } else {
        // ---- fused qkv epilogue: this warp owns 32 cols = exactly one head slice
        const int cb = col0 + wn * 32;             // global column base (mult of 32)
        const int region = cb >> 9;                // 0:q 1:k 2:v
        const int h = (cb >> 5) & 15;
        float qscale = 0.0f;
        if (region == 0)
            qscale = log1pf(expf(temp[h])) * sls[0] * LOG2E;
        float bb[4][2];
        float qev[4][2];
#pragma unroll
        for (int nt = 0; nt < 4; nt++) {
            const int c = cb + nt * 8 + 2 * tig;
            bb[nt][0] = bias[c]; bb[nt][1] = bias[c + 1];
            if (region == 0) {
                qev[nt][0] = qe[h * HD + (c & 31)];
                qev[nt][1] = qe[h * HD + ((c + 1) & 31)];
            }
        }
        bf16* dsthi = (region == 0) ? Qhi : (region == 1) ? Khi : Vhi;
        bf16* dstlo = (region == 0) ? Qlo : (region == 1) ? Klo : Vlo;

#pragma unroll
        for (int mt = 0; mt < 4; mt++) {
#pragma unroll
            for (int half = 0; half < 2; half++) {
                const int r = row0 + wm * 64 + mt * 16 + gid + half * 8;
                const int b = r >> 10, n = r & 1023;
                float v[4][2];
                float s2 = 0.0f;
#pragma unroll
                for (int nt = 0; nt < 4; nt++) {
                    v[nt][0] = acc[mt][nt][2 * half + 0] + bb[nt][0];
                    v[nt][1] = acc[mt][nt][2 * half + 1] + bb[nt][1];
                    s2 = fmaf(v[nt][0], v[nt][0], fmaf(v[nt][1], v[nt][1], s2));
                }
                if (region < 2) {
                    s2 += __shfl_xor_sync(0xffffffffu, s2, 1);
                    s2 += __shfl_xor_sync(0xffffffffu, s2, 2);
                    const float inv = 1.0f / fmaxf(sqrtf(s2), 1e-12f);
#pragma unroll
                    for (int nt = 0; nt < 4; nt++) {
                        if (region == 0) {
                            v[nt][0] = (v[nt][0] * inv + qev[nt][0]) * qscale;
                            v[nt][1] = (v[nt][1] * inv + qev[nt][1]) * qscale;
                        } else {
                            v[nt][0] *= inv;
                            v[nt][1] *= inv;
                        }
                    }
                }
                const size_t obase = ((((size_t)b * HEADS + h) << 10) + n) * HD;
#pragma unroll
                for (int nt = 0; nt < 4; nt++) {
                    const int d = nt * 8 + 2 * tig;
                    bf16 h0, l0, h1, l1;
                    splitf(v[nt][0], h0, l0);
                    splitf(v[nt][1], h1, l1);
                    ((unsigned*)dsthi)[(obase + d) >> 1] =
                        packbf(__bfloat162float(h0), __bfloat162float(h1));
                    ((unsigned*)dstlo)[(obase + d) >> 1] =
                        packbf(__bfloat162float(l0), __bfloat162float(l1));
                }
            }
        }
    }
}

// ---------------------------------------------------------------------------
// Kernel: bf16-split flash attention, 2-stage cp.async pipeline, exp2 softmax.
// Block = (b, h, 128-query tile), 8 warps x 16 q-rows, key tiles of 64.
// smem: 2 stages x [Khi|Klo|Vhi|Vlo] 64x40 bf16 + P hi/lo per warp.
// ---------------------------------------------------------------------------
#define KROW 40
#define KPS  (64 * KROW * 2)            // 5120B per plane
#define STG  (4 * KPS)                  // 20480B per stage
#define PWU  36
#define PBASE (2 * STG)                 // 40960
#define PWSZ (16 * PWU * 4)             // 2304B
#define ATTN_SMEM (PBASE + 8 * 2 * PWSZ)  // 77824B

__global__ __launch_bounds__(256, 2)
void attn_mma(const bf16* __restrict__ Qhi_, const bf16* __restrict__ Qlo_,
              const bf16* __restrict__ Khi_, const bf16* __restrict__ Klo_,
              const bf16* __restrict__ Vhi_, const bf16* __restrict__ Vlo_,
              const bf16* __restrict__ rb, bf16* __restrict__ outhi,
              bf16* __restrict__ outlo)
{
    extern __shared__ __align__(16) char smraw[];
    const uint32_t smb = (uint32_t)__cvta_generic_to_shared(smraw);

    const int tid = threadIdx.x;
    const int w = tid >> 5, lane = tid & 31;
    const int gid = lane >> 2, tig = lane & 3;
    const int q0 = blockIdx.x * 128, h = blockIdx.y, b = blockIdx.z;
    const size_t bh = ((size_t)b * HEADS + h) * NTOK * HD;
    const bf16* Khg = Khi_ + bh;
    const bf16* Klg = Klo_ + bh;
    const bf16* Vhg = Vhi_ + bh;
    const bf16* Vlg = Vlo_ + bh;
    const bf16* rbh = rb + (size_t)h * NTOK * NTOK;
    const int r0 = q0 + w * 16 + gid;
    const int r1 = r0 + 8;

    const uint32_t koff = (uint32_t)((((lane & 7) | ((lane & 16) >> 1)) * KROW + (lane & 8)) * 2);
    const uint32_t voff = (uint32_t)((((lane & 7) | (lane & 8)) * KROW + ((lane & 16) >> 1)) * 2);
    const uint32_t poff = (uint32_t)((((lane & 7) | (lane & 8)) * PWU + ((lane & 16) >> 2)) * 4);
    const uint32_t pwh = smb + PBASE + (uint32_t)w * (2 * PWSZ);
    const uint32_t pwl = pwh + PWSZ;
    unsigned* PwH = (unsigned*)(smraw + PBASE + w * (2 * PWSZ));
    unsigned* PwL = (unsigned*)(smraw + PBASE + w * (2 * PWSZ) + PWSZ);

    // Q fragments (hi/lo) from global
    unsigned qh[2][4], ql[2][4];
#pragma unroll
    for (int kt = 0; kt < 2; kt++) {
        const int d0 = kt * 16 + 2 * tig;
        qh[kt][0] = *(const unsigned*)(Qhi_ + bh + (size_t)r0 * HD + d0);
        qh[kt][1] = *(const unsigned*)(Qhi_ + bh + (size_t)r1 * HD + d0);
        qh[kt][2] = *(const unsigned*)(Qhi_ + bh + (size_t)r0 * HD + d0 + 8);
        qh[kt][3] = *(const unsigned*)(Qhi_ + bh + (size_t)r1 * HD + d0 + 8);
        ql[kt][0] = *(const unsigned*)(Qlo_ + bh + (size_t)r0 * HD + d0);
        ql[kt][1] = *(const unsigned*)(Qlo_ + bh + (size_t)r1 * HD + d0);
        ql[kt][2] = *(const unsigned*)(Qlo_ + bh + (size_t)r0 * HD + d0 + 8);
        ql[kt][3] = *(const unsigned*)(Qlo_ + bh + (size_t)r1 * HD + d0 + 8);
    }

    float o[4][4];
#pragma unroll
    for (int i = 0; i < 4; i++)
#pragma unroll
        for (int j = 0; j < 4; j++) o[i][j] = 0.0f;
    float m0 = -CUDART_INF_F, m1 = -CUDART_INF_F, l0 = 0.0f, l1 = 0.0f;

    // per-thread cp.async of one 16B chunk per plane into stage buf
#define ATTN_LOAD(t, buf)                                                      \
    {                                                                          \
        const int r_ = tid >> 2, q_ = tid & 3;                                 \
        const uint32_t d_ = smb + (buf) * STG + (uint32_t)(r_ * 80 + q_ * 16); \
        const size_t g_ = (size_t)((t) * 64 + r_) * HD + q_ * 8;               \
        cp16(d_,           Khg + g_);                                          \
        cp16(d_ + KPS,     Klg + g_);                                          \
        cp16(d_ + 2 * KPS, Vhg + g_);                                          \
        cp16(d_ + 3 * KPS, Vlg + g_);                                          \
        CP_COMMIT();                                                           \
    }

    ATTN_LOAD(0, 0);

    for (int t = 0; t < 16; t++) {
        if (t < 15) ATTN_LOAD(t + 1, (t + 1) & 1);
        const int key0 = t * 64;

        // S accumulators initialized with gathered bias (overlaps cp.async)
        float s[8][4];
#pragma unroll
        for (int nt = 0; nt < 8; nt++) {
            const float2 u0 = __bfloat1622float2(
                *(const __nv_bfloat162*)(rbh + ((size_t)r0 << 10) + key0 + nt * 8 + 2 * tig));
            const float2 u1 = __bfloat1622float2(
                *(const __nv_bfloat162*)(rbh + ((size_t)r1 << 10) + key0 + nt * 8 + 2 * tig));
            s[nt][0] = u0.x; s[nt][1] = u0.y; s[nt][2] = u1.x; s[nt][3] = u1.y;
        }

        if (t < 15) { CP_WAIT1(); } else { CP_WAIT0(); }
        __syncthreads();
        const uint32_t base = smb + (t & 1) * STG;

        // ---- S += Q K^T (3xBF16)
#pragma unroll
        for (int kt = 0; kt < 2; kt++) {
#pragma unroll
            for (int ntp = 0; ntp < 4; ntp++) {
                const uint32_t ka = base + koff + (uint32_t)(ntp * 1280 + kt * 32);
                unsigned kh0, kh1, kh2, kh3, kl0, kl1, kl2, kl3;
                ldsm_x4(kh0, kh1, kh2, kh3, ka);
                ldsm_x4(kl0, kl1, kl2, kl3, ka + KPS);
                mma16(s[2*ntp],   qh[kt], kh0, kh1);
                mma16(s[2*ntp],   ql[kt], kh0, kh1);
                mma16(s[2*ntp],   qh[kt], kl0, kl1);
                mma16(s[2*ntp+1], qh[kt], kh2, kh3);
                mma16(s[2*ntp+1], ql[kt], kh2, kh3);
                mma16(s[2*ntp+1], qh[kt], kl2, kl3);
            }
        }

        // ---- online softmax (base-2 domain)
        float mx0 = s[0][0], mx1 = s[0][2];
#pragma unroll
        for (int nt = 0; nt < 8; nt++) {
            mx0 = fmaxf(mx0, fmaxf(s[nt][0], s[nt][1]));
            mx1 = fmaxf(mx1, fmaxf(s[nt][2], s[nt][3]));
        }
        mx0 = fmaxf(mx0, __shfl_xor_sync(0xffffffffu, mx0, 1));
        mx0 = fmaxf(mx0, __shfl_xor_sync(0xffffffffu, mx0, 2));
        mx1 = fmaxf(mx1, __shfl_xor_sync(0xffffffffu, mx1, 1));
        mx1 = fmaxf(mx1, __shfl_xor_sync(0xffffffffu, mx1, 2));
        const float mn0 = fmaxf(m0, mx0), mn1 = fmaxf(m1, mx1);
        const float cf0 = ex2(m0 - mn0), cf1 = ex2(m1 - mn1);
        float sum0 = 0.0f, sum1 = 0.0f;
#pragma unroll
        for (int nt = 0; nt < 8; nt++) {
            s[nt][0] = ex2(s[nt][0] - mn0);
            s[nt][1] = ex2(s[nt][1] - mn0);
            s[nt][2] = ex2(s[nt][2] - mn1);
            s[nt][3] = ex2(s[nt][3] - mn1);
            sum0 += s[nt][0] + s[nt][1];
            sum1 += s[nt][2] + s[nt][3];
        }
        sum0 += __shfl_xor_sync(0xffffffffu, sum0, 1);
        sum0 += __shfl_xor_sync(0xffffffffu, sum0, 2);
        sum1 += __shfl_xor_sync(0xffffffffu, sum1, 1);
        sum1 += __shfl_xor_sync(0xffffffffu, sum1, 2);
        l0 = l0 * cf0 + sum0;
        l1 = l1 * cf1 + sum1;
        m0 = mn0; m1 = mn1;
#pragma unroll
        for (int dnt = 0; dnt < 4; dnt++) {
            o[dnt][0] *= cf0; o[dnt][1] *= cf0;
            o[dnt][2] *= cf1; o[dnt][3] *= cf1;
        }

        // ---- stage P hi/lo to per-warp smem as packed bf16x2
#pragma unroll
        for (int nt = 0; nt < 8; nt++) {
            const int cu = nt * 4 + tig;
            {
                const float hx = __bfloat162float(__float2bfloat16_rn(s[nt][0]));
                const float hy = __bfloat162float(__float2bfloat16_rn(s[nt][1]));
                PwH[gid * PWU + cu] = packbf(s[nt][0], s[nt][1]);
                PwL[gid * PWU + cu] = packbf(s[nt][0] - hx, s[nt][1] - hy);
            }
            {
                const float hx = __bfloat162float(__float2bfloat16_rn(s[nt][2]));
                const float hy = __bfloat162float(__float2bfloat16_rn(s[nt][3]));
                PwH[(gid + 8) * PWU + cu] = packbf(s[nt][2], s[nt][3]);
                PwL[(gid + 8) * PWU + cu] = packbf(s[nt][2] - hx, s[nt][3] - hy);
            }
        }
        __syncwarp();

        // ---- O += P V (3xBF16)
#pragma unroll
        for (int kt = 0; kt < 4; kt++) {
            unsigned ph[4], pl[4];
            ldsm_x4(ph[0], ph[1], ph[2], ph[3], pwh + poff + kt * 32);
            ldsm_x4(pl[0], pl[1], pl[2], pl[3], pwl + poff + kt * 32);
#pragma unroll
            for (int ntp = 0; ntp < 2; ntp++) {
                const uint32_t va = base + 2 * KPS + voff + (uint32_t)(kt * 1280 + ntp * 32);
                unsigned vh0, vh1, vh2, vh3, vl0, vl1, vl2, vl3;
                ldsm_x4t(vh0, vh1, vh2, vh3, va);
                ldsm_x4t(vl0, vl1, vl2, vl3, va + KPS);
                mma16(o[2*ntp],   ph, vh0, vh1);
                mma16(o[2*ntp],   pl, vh0, vh1);
                mma16(o[2*ntp],   ph, vl0, vl1);
                mma16(o[2*ntp+1], ph, vh2, vh3);
                mma16(o[2*ntp+1], pl, vh2, vh3);
                mma16(o[2*ntp+1], ph, vl2, vl3);
            }
        }
        __syncthreads();   // stage (t&1) free before iter t+1 refills it
    }

    // ---- epilogue: normalize, split hi/lo, write packed pairs
    const float inv0 = 1.0f / l0, inv1 = 1.0f / l1;
#pragma unroll
    for (int dnt = 0; dnt < 4; dnt++) {
        const int c = h * HD + dnt * 8 + 2 * tig;
        {
            const float v0 = o[dnt][0] * inv0, v1 = o[dnt][1] * inv0;
            const float h0 = __bfloat162float(__float2bfloat16_rn(v0));
            const float h1 = __bfloat162float(__float2bfloat16_rn(v1));
            const size_t u = ((size_t)(((size_t)b << 10) + r0) * DIM + c) >> 1;
            ((unsigned*)outhi)[u] = packbf(v0, v1);
            ((unsigned*)outlo)[u] = packbf(v0 - h0, v1 - h1);
        }
        {
            const float v0 = o[dnt][2] * inv1, v1 = o[dnt][3] * inv1;
            const float h0 = __bfloat162float(__float2bfloat16_rn(v0));
            const float h1 = __bfloat162float(__float2bfloat16_rn(v1));
            const size_t u = ((size_t)(((size_t)b << 10) + r1) * DIM + c) >> 1;
            ((unsigned*)outhi)[u] = packbf(v0, v1);
            ((unsigned*)outlo)[u] = packbf(v0 - h0, v1 - h1);
        }
    }
}

// ---------------------------------------------------------------------------
extern "C" void kernel_launch(void* const* d_in, const int* in_sizes, int n_in,
                              void* d_out, int out_size)
{
    (void)in_sizes; (void)n_in; (void)out_size;
    const float* x      = (const float*)d_in[0];
    const float* qkv_w  = (const float*)d_in[1];
    const float* qkv_b  = (const float*)d_in[2];
    const float* proj_w = (const float*)d_in[3];
    const float* proj_b = (const float*)d_in[4];
    const float* temp   = (const float*)d_in[5];
    const float* qe     = (const float*)d_in[6];
    const float* c1w    = (const float*)d_in[7];
    const float* c1b    = (const float*)d_in[8];
    const float* c2w    = (const float*)d_in[9];
    const float* c2b    = (const float*)d_in[10];
    const float* rct    = (const float*)d_in[11];
    const int*   rpi    = (const int*)d_in[12];
    const float* sls    = (const float*)d_in[13];
    float* out = (float*)d_out;

    float *tt_s;
    bf16 *xhi, *xlo, *wqhi, *wqlo, *wphi, *wplo;
    bf16 *Qhi, *Qlo, *Khi, *Klo, *Vhi, *Vlo, *ahi, *alo, *rb_s;
    cudaGetSymbolAddress((void**)&tt_s,  g_tt);
    cudaGetSymbolAddress((void**)&xhi,  g_xhi);  cudaGetSymbolAddress((void**)&xlo,  g_xlo);
    cudaGetSymbolAddress((void**)&wqhi, g_wqhi); cudaGetSymbolAddress((void**)&wqlo, g_wqlo);
    cudaGetSymbolAddress((void**)&wphi, g_wphi); cudaGetSymbolAddress((void**)&wplo, g_wplo);
    cudaGetSymbolAddress((void**)&Qhi,  g_Qhi);  cudaGetSymbolAddress((void**)&Qlo,  g_Qlo);
    cudaGetSymbolAddress((void**)&Khi,  g_Khi);  cudaGetSymbolAddress((void**)&Klo,  g_Klo);
    cudaGetSymbolAddress((void**)&Vhi,  g_Vhi);  cudaGetSymbolAddress((void**)&Vlo,  g_Vlo);
    cudaGetSymbolAddress((void**)&ahi,  g_ahi);  cudaGetSymbolAddress((void**)&alo,  g_alo);
    cudaGetSymbolAddress((void**)&rb_s, g_rb);

    cudaFuncSetAttribute(attn_mma, cudaFuncAttributeMaxDynamicSharedMemorySize, ATTN_SMEM);
    cudaFuncSetAttribute(gemm_bs<0>, cudaFuncAttributeMaxDynamicSharedMemorySize, 2 * GBUF);
    cudaFuncSetAttribute(gemm_bs<1>, cudaFuncAttributeMaxDynamicSharedMemorySize, 2 * GBUF);

    // 1. CPB MLP + bias materialization (log2e-scaled)
    cpb_kernel<<<TBL, 512>>>(rct, c1w, c1b, c2w, c2b, tt_s);
    rb_kernel<<<dim3(NTOK, HEADS), 256>>>(rpi, tt_s, rb_s);

    // 2. split x and weights into bf16 hi/lo planes
    split_kernel<<<(B_ * NTOK * DIM / 4 + 255) / 256, 256>>>(x, xhi, xlo, B_ * NTOK * DIM);
    split_kernel<<<(3 * DIM * DIM / 4 + 255) / 256, 256>>>(qkv_w, wqhi, wqlo, 3 * DIM * DIM);
    split_kernel<<<(DIM * DIM / 4 + 255) / 256, 256>>>(proj_w, wphi, wplo, DIM * DIM);

    // 3. qkv projection with fused norm/split epilogue -> Q/K/V hi/lo planes
    gemm_bs<1><<<dim3(12, 64), 256, 2 * GBUF>>>(
        xhi, xlo, wqhi, wqlo, qkv_b, nullptr, B_ * NTOK, 3 * DIM, DIM,
        temp, qe, sls, Qhi, Qlo, Khi, Klo, Vhi, Vlo);

    // 4. fused tensor-core attention -> bf16 hi/lo planes
    attn_mma<<<dim3(NTOK / 128, HEADS, B_), 256, ATTN_SMEM>>>(
        Qhi, Qlo, Khi, Klo, Vhi, Vlo, rb_s, ahi, alo);

    // 5. output projection -> fp32 out
    gemm_bs<0><<<dim3(4, 64), 256, 2 * GBUF>>>(
        ahi, alo, wphi, wplo, proj_b, out, B_ * NTOK, DIM, DIM,
        nullptr, nullptr, nullptr,
        nullptr, nullptr, nullptr, nullptr, nullptr, nullptr);
}

// round 5
// speedup vs baseline: 2.7962x; 1.0704x over previous
#include <cuda_runtime.h>
#include <cuda_bf16.h>
#include <cstdint>
#include <math.h>
#include <math_constants.h>

#define B_     8
#define NTOK   1024
#define DIM    512
#define HEADS  16
#define HD     32
#define TBL    3969
#define LOG2E  1.4426950408889634f
#define SMSHIFT 48.0f     // fixed softmax offset (base-2); |logit| < 48 guaranteed

typedef __nv_bfloat16 bf16;

// ---------------- scratch (device globals; no dynamic allocation) ----------
__device__ bf16  g_xhi[B_ * NTOK * DIM],        g_xlo[B_ * NTOK * DIM];
__device__ bf16  g_wqhi[3 * DIM * DIM],         g_wqlo[3 * DIM * DIM];
__device__ bf16  g_wphi[DIM * DIM],             g_wplo[DIM * DIM];
__device__ bf16  g_Qhi[B_ * HEADS * NTOK * HD], g_Qlo[B_ * HEADS * NTOK * HD];
__device__ bf16  g_Khi[B_ * HEADS * NTOK * HD], g_Klo[B_ * HEADS * NTOK * HD];
__device__ bf16  g_Vhi[B_ * HEADS * NTOK * HD], g_Vlo[B_ * HEADS * NTOK * HD];
__device__ bf16  g_ahi[B_ * NTOK * DIM],        g_alo[B_ * NTOK * DIM];
__device__ bf16  g_rb [HEADS * NTOK * NTOK];                 // bias * log2e
__device__ float g_tt [HEADS * TBL];

// ---------------------------------------------------------------------------
// helpers
// ---------------------------------------------------------------------------
__device__ __forceinline__ void mma16(float* d, const unsigned* a, unsigned b0, unsigned b1) {
    asm volatile("mma.sync.aligned.m16n8k16.row.col.f32.bf16.bf16.f32 "
                 "{%0,%1,%2,%3}, {%4,%5,%6,%7}, {%8,%9}, {%0,%1,%2,%3};"
                 : "+f"(d[0]), "+f"(d[1]), "+f"(d[2]), "+f"(d[3])
                 : "r"(a[0]), "r"(a[1]), "r"(a[2]), "r"(a[3]), "r"(b0), "r"(b1));
}
__device__ __forceinline__ void ldsm_x4(unsigned& r0, unsigned& r1, unsigned& r2,
                                        unsigned& r3, unsigned addr) {
    asm volatile("ldmatrix.sync.aligned.m8n8.x4.shared.b16 {%0,%1,%2,%3}, [%4];"
                 : "=r"(r0), "=r"(r1), "=r"(r2), "=r"(r3) : "r"(addr));
}
__device__ __forceinline__ void ldsm_x4t(unsigned& r0, unsigned& r1, unsigned& r2,
                                         unsigned& r3, unsigned addr) {
    asm volatile("ldmatrix.sync.aligned.m8n8.x4.trans.shared.b16 {%0,%1,%2,%3}, [%4];"
                 : "=r"(r0), "=r"(r1), "=r"(r2), "=r"(r3) : "r"(addr));
}
__device__ __forceinline__ void cp16(uint32_t dst, const void* src) {
    asm volatile("cp.async.cg.shared.global [%0], [%1], 16;" :: "r"(dst), "l"(src));
}
#define CP_COMMIT() asm volatile("cp.async.commit_group;" ::: "memory")
#define CP_WAIT1()  asm volatile("cp.async.wait_group 1;" ::: "memory")
#define CP_WAIT0()  asm volatile("cp.async.wait_group 0;" ::: "memory")

__device__ __forceinline__ unsigned packbf(float a, float b) {
    __nv_bfloat162 h = __floats2bfloat162_rn(a, b);
    return *(unsigned*)&h;
}
__device__ __forceinline__ void splitf(float x, bf16& hi, bf16& lo) {
    hi = __float2bfloat16_rn(x);
    lo = __float2bfloat16_rn(x - __bfloat162float(hi));
}
__device__ __forceinline__ float ex2(float x) {
    float r;
    asm("ex2.approx.ftz.f32 %0, %1;" : "=f"(r) : "f"(x));
    return r;
}

// ---------------------------------------------------------------------------
// Kernel: split fp32 array into bf16 hi/lo planes
// ---------------------------------------------------------------------------
__global__ __launch_bounds__(256)
void split_kernel(const float* __restrict__ in, bf16* __restrict__ hi,
                  bf16* __restrict__ lo, int n)
{
    const int i = (blockIdx.x * 256 + threadIdx.x) * 4;
    if (i >= n) return;
    const float4 v = *(const float4*)(in + i);
    bf16 h0, h1, h2, h3, l0, l1, l2, l3;
    splitf(v.x, h0, l0); splitf(v.y, h1, l1);
    splitf(v.z, h2, l2); splitf(v.w, h3, l3);
    ((uint2*)hi)[i >> 2] = make_uint2(packbf(__bfloat162float(h0), __bfloat162float(h1)),
                                      packbf(__bfloat162float(h2), __bfloat162float(h3)));
    ((uint2*)lo)[i >> 2] = make_uint2(packbf(__bfloat162float(l0), __bfloat162float(l1)),
                                      packbf(__bfloat162float(l2), __bfloat162float(l3)));
}

// ---------------------------------------------------------------------------
// Kernel: continuous position bias MLP
// ---------------------------------------------------------------------------
__global__ __launch_bounds__(512)
void cpb_kernel(const float* __restrict__ tbl, const float* __restrict__ w1,
                const float* __restrict__ b1, const float* __restrict__ w2,
                const float* __restrict__ b2, float* __restrict__ tt)
{
    __shared__ float hid[512];
    const int r = blockIdx.x;
    const int tid = threadIdx.x;
    const float c0 = tbl[r * 2 + 0];
    const float c1 = tbl[r * 2 + 1];
    hid[tid] = fmaxf(fmaf(c0, w1[tid * 2 + 0], fmaf(c1, w1[tid * 2 + 1], b1[tid])), 0.0f);
    __syncthreads();
    const int w = tid >> 5, lane = tid & 31;
    float s = 0.0f;
#pragma unroll
    for (int i = 0; i < 512; i += 32)
        s = fmaf(hid[i + lane], w2[w * 512 + i + lane], s);
#pragma unroll
    for (int msk = 16; msk >= 1; msk >>= 1)
        s += __shfl_xor_sync(0xffffffffu, s, msk);
    if (lane == 0)
        tt[w * TBL + r] = s + b2[w];
}

// ---------------------------------------------------------------------------
// Kernel: materialize rb[h][q][k] = bf16(log2e * tt[h][idx[q*1024+k]])
// ---------------------------------------------------------------------------
__global__ __launch_bounds__(256)
void rb_kernel(const int* __restrict__ idx, const float* __restrict__ tt,
               bf16* __restrict__ rb)
{
    const int q = blockIdx.x, h = blockIdx.y;
    const int k = threadIdx.x * 4;
    const int4 id = *(const int4*)(idx + q * NTOK + k);
    const float* tth = tt + h * TBL;
    ((uint2*)rb)[(((size_t)h * NTOK + q) * NTOK + k) >> 2] =
        make_uint2(packbf(tth[id.x] * LOG2E, tth[id.y] * LOG2E),
                   packbf(tth[id.z] * LOG2E, tth[id.w] * LOG2E));
}

// ---------------------------------------------------------------------------
// Kernel: 3xBF16 split NT-GEMM. 128x128 tile, k-step 32, 8 warps (2m x 4n).
// MODE 0: C fp32 = A B^T + bias.
// MODE 1: fused qkv epilogue — per-head l2norm (+query-embed, temp scale,
//         log2e fold for q), split into bf16 hi/lo planes [b][h][n][32].
// ---------------------------------------------------------------------------
#define GBUF 40960
#define GROW 40

template<int MODE>
__global__ __launch_bounds__(256, 2)
void gemm_bs(const bf16* __restrict__ Ahi, const bf16* __restrict__ Alo,
             const bf16* __restrict__ Bhi, const bf16* __restrict__ Blo,
             const float* __restrict__ bias, float* __restrict__ C,
             int M, int N, int K,
             const float* __restrict__ temp, const float* __restrict__ qe,
             const float* __restrict__ sls,
             bf16* __restrict__ Qhi, bf16* __restrict__ Qlo,
             bf16* __restrict__ Khi, bf16* __restrict__ Klo,
             bf16* __restrict__ Vhi, bf16* __restrict__ Vlo)
{
    extern __shared__ __align__(16) char smraw[];
    const uint32_t smb = (uint32_t)__cvta_generic_to_shared(smraw);

    const int tid = threadIdx.x;
    const int w = tid >> 5, lane = tid & 31;
    const int gid = lane >> 2, tig = lane & 3;
    const int wm = w >> 2, wn = w & 3;
    const int row0 = blockIdx.y * 128, col0 = blockIdx.x * 128;
    const int NS = K / 32;

    const int rowA = (lane & 7) | (lane & 8);
    const uint32_t aoff = (uint32_t)(rowA * GROW + ((lane & 16) >> 1)) * 2;
    const int rowB = (lane & 7) | ((lane & 16) >> 1);
    const uint32_t boff = (uint32_t)(rowB * GROW + (lane & 8)) * 2;

    float acc[4][4][4];
#pragma unroll
    for (int i = 0; i < 4; i++)
#pragma unroll
        for (int j = 0; j < 4; j++)
#pragma unroll
            for (int q = 0; q < 4; q++) acc[i][j][q] = 0.0f;

#define GEMM_LOAD(s, buf)                                                          \
    {                                                                              \
        const int k0_ = (s) * 32;                                                  \
        _Pragma("unroll")                                                          \
        for (int i_ = 0; i_ < 2; i_++) {                                           \
            const int slot_ = tid + i_ * 256;                                      \
            const int r_ = slot_ >> 2, q_ = slot_ & 3;                             \
            const uint32_t d_ = smb + (buf) * GBUF + (uint32_t)(r_ * 80 + q_ * 16);\
            const size_t ga_ = (size_t)(row0 + r_) * K + k0_ + q_ * 8;             \
            const size_t gb_ = (size_t)(col0 + r_) * K + k0_ + q_ * 8;             \
            cp16(d_,         Ahi + ga_);                                           \
            cp16(d_ + 10240, Alo + ga_);                                           \
            cp16(d_ + 20480, Bhi + gb_);                                           \
            cp16(d_ + 30720, Blo + gb_);                                           \
        }                                                                          \
        CP_COMMIT();                                                               \
    }

    GEMM_LOAD(0, 0);
    GEMM_LOAD(1, 1);

    for (int s = 0; s < NS; s++) {
        if (s < NS - 1) { CP_WAIT1(); } else { CP_WAIT0(); }
        __syncthreads();
        const uint32_t base = smb + (s & 1) * GBUF;
#pragma unroll
        for (int kt = 0; kt < 2; kt++) {
            unsigned bh[4][2], bl[4][2];
#pragma unroll
            for (int ntp = 0; ntp < 2; ntp++) {
                const uint32_t ba = base + 20480 + boff
                                  + (uint32_t)((wn * 32 + ntp * 16) * 80 + kt * 32);
                ldsm_x4(bh[2*ntp][0], bh[2*ntp][1], bh[2*ntp+1][0], bh[2*ntp+1][1], ba);
                ldsm_x4(bl[2*ntp][0], bl[2*ntp][1], bl[2*ntp+1][0], bl[2*ntp+1][1], ba + 10240);
            }
#pragma unroll
            for (int mt = 0; mt < 4; mt++) {
                const uint32_t aa = base + aoff
                                  + (uint32_t)((wm * 64 + mt * 16) * 80 + kt * 32);
                unsigned ah[4], al[4];
                ldsm_x4(ah[0], ah[1], ah[2], ah[3], aa);
                ldsm_x4(al[0], al[1], al[2], al[3], aa + 10240);
#pragma unroll
                for (int nt = 0; nt < 4; nt++) {
                    mma16(acc[mt][nt], ah, bh[nt][0], bh[nt][1]);
                    mma16(acc[mt][nt], al, bh[nt][0], bh[nt][1]);
                    mma16(acc[mt][nt], ah, bl[nt][0], bl[nt][1]);
                }
            }
        }
        __syncthreads();
        if (s + 2 < NS) GEMM_LOAD(s + 2, s & 1);
    }

    if (MODE == 0) {
#pragma unroll
        for (int mt = 0; mt < 4; mt++) {
            const int ra = row0 + wm * 64 + mt * 16 + gid;
#pragma unroll
            for (int nt = 0; nt < 4; nt++) {
                const int c = col0 + wn * 32 + nt * 8 + 2 * tig;
                const float bb0 = bias[c], bb1 = bias[c + 1];
                *(float2*)(C + (size_t)ra * N + c) =
                    make_float2(acc[mt][nt][0] + bb0, acc[mt][nt][1] + bb1);
                *(float2*)(C + (size_t)(ra + 8) * N + c) =
                    make_float2(acc[mt][nt][2] + bb0, acc[mt][nt][3] + bb1);
            }
        }
    } else {
        // ---- fused qkv epilogue: this warp owns 32 cols = exactly one head slice
        const int cb = col0 + wn * 32;
        const int region = cb >> 9;                // 0:q 1:k 2:v
        const int h = (cb >> 5) & 15;
        float qscale = 0.0f;
        if (region == 0)
            qscale = log1pf(expf(temp[h])) * sls[0] * LOG2E;
        float bb[4][2];
        float qev[4][2];
#pragma unroll
        for (int nt = 0; nt < 4; nt++) {
            const int c = cb + nt * 8 + 2 * tig;
            bb[nt][0] = bias[c]; bb[nt][1] = bias[c + 1];
            if (region == 0) {
                qev[nt][0] = qe[h * HD + (c & 31)];
                qev[nt][1] = qe[h * HD + ((c + 1) & 31)];
            }
        }
        bf16* dsthi = (region == 0) ? Qhi : (region == 1) ? Khi : Vhi;
        bf16* dstlo = (region == 0) ? Qlo : (region == 1) ? Klo : Vlo;

#pragma unroll
        for (int mt = 0; mt < 4; mt++) {
#pragma unroll
            for (int half = 0; half < 2; half++) {
                const int r = row0 + wm * 64 + mt * 16 + gid + half * 8;
                const int b = r >> 10, n = r & 1023;
                float v[4][2];
                float s2 = 0.0f;
#pragma unroll
                for (int nt = 0; nt < 4; nt++) {
                    v[nt][0] = acc[mt][nt][2 * half + 0] + bb[nt][0];
                    v[nt][1] = acc[mt][nt][2 * half + 1] + bb[nt][1];
                    s2 = fmaf(v[nt][0], v[nt][0], fmaf(v[nt][1], v[nt][1], s2));
                }
                if (region < 2) {
                    s2 += __shfl_xor_sync(0xffffffffu, s2, 1);
                    s2 += __shfl_xor_sync(0xffffffffu, s2, 2);
                    const float inv = 1.0f / fmaxf(sqrtf(s2), 1e-12f);
#pragma unroll
                    for (int nt = 0; nt < 4; nt++) {
                        if (region == 0) {
                            v[nt][0] = (v[nt][0] * inv + qev[nt][0]) * qscale;
                            v[nt][1] = (v[nt][1] * inv + qev[nt][1]) * qscale;
                        } else {
                            v[nt][0] *= inv;
                            v[nt][1] *= inv;
                        }
                    }
                }
                const size_t obase = ((((size_t)b * HEADS + h) << 10) + n) * HD;
#pragma unroll
                for (int nt = 0; nt < 4; nt++) {
                    const int d = nt * 8 + 2 * tig;
                    bf16 h0, l0, h1, l1;
                    splitf(v[nt][0], h0, l0);
                    splitf(v[nt][1], h1, l1);
                    ((unsigned*)dsthi)[(obase + d) >> 1] =
                        packbf(__bfloat162float(h0), __bfloat162float(h1));
                    ((unsigned*)dstlo)[(obase + d) >> 1] =
                        packbf(__bfloat162float(l0), __bfloat162float(l1));
                }
            }
        }
    }
}

// ---------------------------------------------------------------------------
// Kernel: bf16-split flash attention, fixed-offset softmax, register-direct P.
// Block = (b, h, 128-query tile), 8 warps x 16 q-rows, key tiles of 64.
// Grid x=batch so blocks sharing rb rows run concurrently (L2 reuse).
// smem: 2 stages x [Khi|Klo|Vhi|Vlo] 64x40 bf16 = 40KB total. No P buffer.
// ---------------------------------------------------------------------------
#define KROW 40
#define KPS  (64 * KROW * 2)            // 5120B per plane
#define STG  (4 * KPS)                  // 20480B per stage
#define ATTN_SMEM (2 * STG)             // 40960B

__global__ __launch_bounds__(256, 2)
void attn_mma(const bf16* __restrict__ Qhi_, const bf16* __restrict__ Qlo_,
              const bf16* __restrict__ Khi_, const bf16* __restrict__ Klo_,
              const bf16* __restrict__ Vhi_, const bf16* __restrict__ Vlo_,
              const bf16* __restrict__ rb, bf16* __restrict__ outhi,
              bf16* __restrict__ outlo)
{
    extern __shared__ __align__(16) char smraw[];
    const uint32_t smb = (uint32_t)__cvta_generic_to_shared(smraw);

    const int tid = threadIdx.x;
    const int w = tid >> 5, lane = tid & 31;
    const int gid = lane >> 2, tig = lane & 3;
    const int b = blockIdx.x, h = blockIdx.y, q0 = blockIdx.z * 128;
    const size_t bh = ((size_t)b * HEADS + h) * NTOK * HD;
    const bf16* Khg = Khi_ + bh;
    const bf16* Klg = Klo_ + bh;
    const bf16* Vhg = Vhi_ + bh;
    const bf16* Vlg = Vlo_ + bh;
    const bf16* rbh = rb + (size_t)h * NTOK * NTOK;
    const int r0 = q0 + w * 16 + gid;
    const int r1 = r0 + 8;

    const uint32_t koff = (uint32_t)((((lane & 7) | ((lane & 16) >> 1)) * KROW + (lane & 8)) * 2);
    const uint32_t voff = (uint32_t)((((lane & 7) | (lane & 8)) * KROW + ((lane & 16) >> 1)) * 2);

    // Q fragments (hi/lo) from global
    unsigned qh[2][4], ql[2][4];
#pragma unroll
    for (int kt = 0; kt < 2; kt++) {
        const int d0 = kt * 16 + 2 * tig;
        qh[kt][0] = *(const unsigned*)(Qhi_ + bh + (size_t)r0 * HD + d0);
        qh[kt][1] = *(const unsigned*)(Qhi_ + bh + (size_t)r1 * HD + d0);
        qh[kt][2] = *(const unsigned*)(Qhi_ + bh + (size_t)r0 * HD + d0 + 8);
        qh[kt][3] = *(const unsigned*)(Qhi_ + bh + (size_t)r1 * HD + d0 + 8);
        ql[kt][0] = *(const unsigned*)(Qlo_ + bh + (size_t)r0 * HD + d0);
        ql[kt][1] = *(const unsigned*)(Qlo_ + bh + (size_t)r1 * HD + d0);
        ql[kt][2] = *(const unsigned*)(Qlo_ + bh + (size_t)r0 * HD + d0 + 8);
        ql[kt][3] = *(const unsigned*)(Qlo_ + bh + (size_t)r1 * HD + d0 + 8);
    }

    float o[4][4];
#pragma unroll
    for (int i = 0; i < 4; i++)
#pragma unroll
        for (int j = 0; j < 4; j++) o[i][j] = 0.0f;
    float l0 = 0.0f, l1 = 0.0f;

#define ATTN_LOAD(t, buf)                                                      \
    {                                                                          \
        const int r_ = tid >> 2, q_ = tid & 3;                                 \
        const uint32_t d_ = smb + (buf) * STG + (uint32_t)(r_ * 80 + q_ * 16); \
        const size_t g_ = (size_t)((t) * 64 + r_) * HD + q_ * 8;               \
        cp16(d_,           Khg + g_);                                          \
        cp16(d_ + KPS,     Klg + g_);                                          \
        cp16(d_ + 2 * KPS, Vhg + g_);                                          \
        cp16(d_ + 3 * KPS, Vlg + g_);                                          \
        CP_COMMIT();                                                           \
    }

    ATTN_LOAD(0, 0);

    for (int t = 0; t < 16; t++) {
        if (t < 15) ATTN_LOAD(t + 1, (t + 1) & 1);
        const int key0 = t * 64;

        // S accumulators initialized with gathered bias (overlaps cp.async)
        float s[8][4];
#pragma unroll
        for (int nt = 0; nt < 8; nt++) {
            const float2 u0 = __bfloat1622float2(
                *(const __nv_bfloat162*)(rbh + ((size_t)r0 << 10) + key0 + nt * 8 + 2 * tig));
            const float2 u1 = __bfloat1622float2(
                *(const __nv_bfloat162*)(rbh + ((size_t)r1 << 10) + key0 + nt * 8 + 2 * tig));
            s[nt][0] = u0.x; s[nt][1] = u0.y; s[nt][2] = u1.x; s[nt][3] = u1.y;
        }

        if (t < 15) { CP_WAIT1(); } else { CP_WAIT0(); }
        __syncthreads();
        const uint32_t base = smb + (t & 1) * STG;

        // ---- S += Q K^T (3xBF16)
#pragma unroll
        for (int kt = 0; kt < 2; kt++) {
#pragma unroll
            for (int ntp = 0; ntp < 4; ntp++) {
                const uint32_t ka = base + koff + (uint32_t)(ntp * 1280 + kt * 32);
                unsigned kh0, kh1, kh2, kh3, kl0, kl1, kl2, kl3;
                ldsm_x4(kh0, kh1, kh2, kh3, ka);
                ldsm_x4(kl0, kl1, kl2, kl3, ka + KPS);
                mma16(s[2*ntp],   qh[kt], kh0, kh1);
                mma16(s[2*ntp],   ql[kt], kh0, kh1);
                mma16(s[2*ntp],   qh[kt], kl0, kl1);
                mma16(s[2*ntp+1], qh[kt], kh2, kh3);
                mma16(s[2*ntp+1], ql[kt], kh2, kh3);
                mma16(s[2*ntp+1], qh[kt], kl2, kl3);
            }
        }

        // ---- fixed-offset softmax: p = 2^(s - 48), accumulate row sums
#pragma unroll
        for (int nt = 0; nt < 8; nt++) {
            s[nt][0] = ex2(s[nt][0] - SMSHIFT);
            s[nt][1] = ex2(s[nt][1] - SMSHIFT);
            s[nt][2] = ex2(s[nt][2] - SMSHIFT);
            s[nt][3] = ex2(s[nt][3] - SMSHIFT);
            l0 += s[nt][0] + s[nt][1];
            l1 += s[nt][2] + s[nt][3];
        }

        // ---- O += P V: P A-fragments built directly from S C-fragments
#pragma unroll
        for (int kt = 0; kt < 4; kt++) {
            unsigned ph[4], pl[4];
#pragma unroll
            for (int half = 0; half < 2; half++) {
                const int nt = 2 * kt + half;
                const unsigned h01 = packbf(s[nt][0], s[nt][1]);
                const unsigned h23 = packbf(s[nt][2], s[nt][3]);
                const float2 f01 = __bfloat1622float2(*(const __nv_bfloat162*)&h01);
                const float2 f23 = __bfloat1622float2(*(const __nv_bfloat162*)&h23);
                ph[2 * half + 0] = h01;
                ph[2 * half + 1] = h23;
                pl[2 * half + 0] = packbf(s[nt][0] - f01.x, s[nt][1] - f01.y);
                pl[2 * half + 1] = packbf(s[nt][2] - f23.x, s[nt][3] - f23.y);
            }
#pragma unroll
            for (int ntp = 0; ntp < 2; ntp++) {
                const uint32_t va = base + 2 * KPS + voff + (uint32_t)(kt * 1280 + ntp * 32);
                unsigned vh0, vh1, vh2, vh3, vl0, vl1, vl2, vl3;
                ldsm_x4t(vh0, vh1, vh2, vh3, va);
                ldsm_x4t(vl0, vl1, vl2, vl3, va + KPS);
                mma16(o[2*ntp],   ph, vh0, vh1);
                mma16(o[2*ntp],   pl, vh0, vh1);
                mma16(o[2*ntp],   ph, vl0, vl1);
                mma16(o[2*ntp+1], ph, vh2, vh3);
                mma16(o[2*ntp+1], pl, vh2, vh3);
                mma16(o[2*ntp+1], ph, vl2, vl3);
            }
        }
        __syncthreads();   // stage (t&1) free before iter t+1 refills it
    }

    // ---- final row-sum reduction across quad lanes
    l0 += __shfl_xor_sync(0xffffffffu, l0, 1);
    l0 += __shfl_xor_sync(0xffffffffu, l0, 2);
    l1 += __shfl_xor_sync(0xffffffffu, l1, 1);
    l1 += __shfl_xor_sync(0xffffffffu, l1, 2);

    // ---- epilogue: normalize, split hi/lo, write packed pairs
    const float inv0 = 1.0f / l0, inv1 = 1.0f / l1;
#pragma unroll
    for (int dnt = 0; dnt < 4; dnt++) {
        const int c = h * HD + dnt * 8 + 2 * tig;
        {
            const float v0 = o[dnt][0] * inv0, v1 = o[dnt][1] * inv0;
            const float h0 = __bfloat162float(__float2bfloat16_rn(v0));
            const float h1 = __bfloat162float(__float2bfloat16_rn(v1));
            const size_t u = ((size_t)(((size_t)b << 10) + r0) * DIM + c) >> 1;
            ((unsigned*)outhi)[u] = packbf(v0, v1);
            ((unsigned*)outlo)[u] = packbf(v0 - h0, v1 - h1);
        }
        {
            const float v0 = o[dnt][2] * inv1, v1 = o[dnt][3] * inv1;
            const float h0 = __bfloat162float(__float2bfloat16_rn(v0));
            const float h1 = __bfloat162float(__float2bfloat16_rn(v1));
            const size_t u = ((size_t)(((size_t)b << 10) + r1) * DIM + c) >> 1;
            ((unsigned*)outhi)[u] = packbf(v0, v1);
            ((unsigned*)outlo)[u] = packbf(v0 - h0, v1 - h1);
        }
    }
}

// ---------------------------------------------------------------------------
extern "C" void kernel_launch(void* const* d_in, const int* in_sizes, int n_in,
                              void* d_out, int out_size)
{
    (void)in_sizes; (void)n_in; (void)out_size;
    const float* x      = (const float*)d_in[0];
    const float* qkv_w  = (const float*)d_in[1];
    const float* qkv_b  = (const float*)d_in[2];
    const float* proj_w = (const float*)d_in[3];
    const float* proj_b = (const float*)d_in[4];
    const float* temp   = (const float*)d_in[5];
    const float* qe     = (const float*)d_in[6];
    const float* c1w    = (const float*)d_in[7];
    const float* c1b    = (const float*)d_in[8];
    const float* c2w    = (const float*)d_in[9];
    const float* c2b    = (const float*)d_in[10];
    const float* rct    = (const float*)d_in[11];
    const int*   rpi    = (const int*)d_in[12];
    const float* sls    = (const float*)d_in[13];
    float* out = (float*)d_out;

    float *tt_s;
    bf16 *xhi, *xlo, *wqhi, *wqlo, *wphi, *wplo;
    bf16 *Qhi, *Qlo, *Khi, *Klo, *Vhi, *Vlo, *ahi, *alo, *rb_s;
    cudaGetSymbolAddress((void**)&tt_s,  g_tt);
    cudaGetSymbolAddress((void**)&xhi,  g_xhi);  cudaGetSymbolAddress((void**)&xlo,  g_xlo);
    cudaGetSymbolAddress((void**)&wqhi, g_wqhi); cudaGetSymbolAddress((void**)&wqlo, g_wqlo);
    cudaGetSymbolAddress((void**)&wphi, g_wphi); cudaGetSymbolAddress((void**)&wplo, g_wplo);
    cudaGetSymbolAddress((void**)&Qhi,  g_Qhi);  cudaGetSymbolAddress((void**)&Qlo,  g_Qlo);
    cudaGetSymbolAddress((void**)&Khi,  g_Khi);  cudaGetSymbolAddress((void**)&Klo,  g_Klo);
    cudaGetSymbolAddress((void**)&Vhi,  g_Vhi);  cudaGetSymbolAddress((void**)&Vlo,  g_Vlo);
    cudaGetSymbolAddress((void**)&ahi,  g_ahi);  cudaGetSymbolAddress((void**)&alo,  g_alo);
    cudaGetSymbolAddress((void**)&rb_s, g_rb);

    cudaFuncSetAttribute(attn_mma, cudaFuncAttributeMaxDynamicSharedMemorySize, ATTN_SMEM);
    cudaFuncSetAttribute(gemm_bs<0>, cudaFuncAttributeMaxDynamicSharedMemorySize, 2 * GBUF);
    cudaFuncSetAttribute(gemm_bs<1>, cudaFuncAttributeMaxDynamicSharedMemorySize, 2 * GBUF);

    // 1. CPB MLP + bias materialization (log2e-scaled)
    cpb_kernel<<<TBL, 512>>>(rct, c1w, c1b, c2w, c2b, tt_s);
    rb_kernel<<<dim3(NTOK, HEADS), 256>>>(rpi, tt_s, rb_s);

    // 2. split x and weights into bf16 hi/lo planes
    split_kernel<<<(B_ * NTOK * DIM / 4 + 255) / 256, 256>>>(x, xhi, xlo, B_ * NTOK * DIM);
    split_kernel<<<(3 * DIM * DIM / 4 + 255) / 256, 256>>>(qkv_w, wqhi, wqlo, 3 * DIM * DIM);
    split_kernel<<<(DIM * DIM / 4 + 255) / 256, 256>>>(proj_w, wphi, wplo, DIM * DIM);

    // 3. qkv projection with fused norm/split epilogue -> Q/K/V hi/lo planes
    gemm_bs<1><<<dim3(12, 64), 256, 2 * GBUF>>>(
        xhi, xlo, wqhi, wqlo, qkv_b, nullptr, B_ * NTOK, 3 * DIM, DIM,
        temp, qe, sls, Qhi, Qlo, Khi, Klo, Vhi, Vlo);

    // 4. fused tensor-core attention (batch fastest for rb L2 reuse)
    attn_mma<<<dim3(B_, HEADS, NTOK / 128), 256, ATTN_SMEM>>>(
        Qhi, Qlo, Khi, Klo, Vhi, Vlo, rb_s, ahi, alo);

    // 5. output projection -> fp32 out
    gemm_bs<0><<<dim3(4, 64), 256, 2 * GBUF>>>(
        ahi, alo, wphi, wplo, proj_b, out, B_ * NTOK, DIM, DIM,
        nullptr, nullptr, nullptr,
        nullptr, nullptr, nullptr, nullptr, nullptr, nullptr);
}

// round 7
// speedup vs baseline: 3.1344x; 1.1209x over previous
#include <cuda_runtime.h>
#include <cuda_bf16.h>
#include <cstdint>
#include <math.h>
#include <math_constants.h>

#define B_     8
#define NTOK   1024
#define DIM    512
#define HEADS  16
#define HD     32
#define TBL    3969
#define LOG2E  1.4426950408889634f
#define SMSHIFT 48.0f

typedef __nv_bfloat16 bf16;

// ---------------- scratch (device globals; no dynamic allocation) ----------
__device__ bf16  g_xhi[B_ * NTOK * DIM],        g_xlo[B_ * NTOK * DIM];
__device__ bf16  g_wqhi[3 * DIM * DIM],         g_wqlo[3 * DIM * DIM];
__device__ bf16  g_wphi[DIM * DIM],             g_wplo[DIM * DIM];
__device__ bf16  g_Qhi[B_ * HEADS * NTOK * HD], g_Qlo[B_ * HEADS * NTOK * HD];
__device__ bf16  g_Khi[B_ * HEADS * NTOK * HD], g_Klo[B_ * HEADS * NTOK * HD];
__device__ bf16  g_Vhi[B_ * HEADS * NTOK * HD], g_Vlo[B_ * HEADS * NTOK * HD];
__device__ bf16  g_ahi[B_ * NTOK * DIM],        g_alo[B_ * NTOK * DIM];
__device__ bf16  g_rb [HEADS * NTOK * NTOK];    // bias * log2e, fragment-major permuted
__device__ float g_tt [HEADS * TBL];

// ---------------------------------------------------------------------------
// helpers
// ---------------------------------------------------------------------------
__device__ __forceinline__ void mma16(float* d, const unsigned* a, unsigned b0, unsigned b1) {
    asm volatile("mma.sync.aligned.m16n8k16.row.col.f32.bf16.bf16.f32 "
                 "{%0,%1,%2,%3}, {%4,%5,%6,%7}, {%8,%9}, {%0,%1,%2,%3};"
                 : "+f"(d[0]), "+f"(d[1]), "+f"(d[2]), "+f"(d[3])
                 : "r"(a[0]), "r"(a[1]), "r"(a[2]), "r"(a[3]), "r"(b0), "r"(b1));
}
__device__ __forceinline__ void ldsm_x4(unsigned& r0, unsigned& r1, unsigned& r2,
                                        unsigned& r3, unsigned addr) {
    asm volatile("ldmatrix.sync.aligned.m8n8.x4.shared.b16 {%0,%1,%2,%3}, [%4];"
                 : "=r"(r0), "=r"(r1), "=r"(r2), "=r"(r3) : "r"(addr));
}
__device__ __forceinline__ void ldsm_x4t(unsigned& r0, unsigned& r1, unsigned& r2,
                                         unsigned& r3, unsigned addr) {
    asm volatile("ldmatrix.sync.aligned.m8n8.x4.trans.shared.b16 {%0,%1,%2,%3}, [%4];"
                 : "=r"(r0), "=r"(r1), "=r"(r2), "=r"(r3) : "r"(addr));
}
__device__ __forceinline__ void cp16(uint32_t dst, const void* src) {
    asm volatile("cp.async.cg.shared.global [%0], [%1], 16;" :: "r"(dst), "l"(src));
}
#define CP_COMMIT() asm volatile("cp.async.commit_group;" ::: "memory")
#define CP_WAIT1()  asm volatile("cp.async.wait_group 1;" ::: "memory")
#define CP_WAIT0()  asm volatile("cp.async.wait_group 0;" ::: "memory")

__device__ __forceinline__ unsigned packbf(float a, float b) {
    __nv_bfloat162 h = __floats2bfloat162_rn(a, b);
    return *(unsigned*)&h;
}
__device__ __forceinline__ void splitf(float x, bf16& hi, bf16& lo) {
    hi = __float2bfloat16_rn(x);
    lo = __float2bfloat16_rn(x - __bfloat162float(hi));
}
__device__ __forceinline__ float ex2(float x) {
    float r;
    asm("ex2.approx.ftz.f32 %0, %1;" : "=f"(r) : "f"(x));
    return r;
}
__device__ __forceinline__ uint32_t smem_u32(const void* p) {
    return (uint32_t)__cvta_generic_to_shared(p);
}

// ---------------------------------------------------------------------------
// Kernel 0: fused prologue — three fp32->bf16 hi/lo splits + CPB MLP.
// Blocks [0, SPLITBLK) split x / qkv_w / proj_w; blocks [SPLITBLK, +TBL) run
// one CPB row each (256 threads: 2 hid each, 8 warps x 2 heads).
// ---------------------------------------------------------------------------
#define XELEM  (B_ * NTOK * DIM)
#define WQELEM (3 * DIM * DIM)
#define WPELEM (DIM * DIM)
#define XBLK   (XELEM / 1024)
#define WQBLK  (WQELEM / 1024)
#define WPBLK  (WPELEM / 1024)
#define SPLITBLK (XBLK + WQBLK + WPBLK)

__global__ __launch_bounds__(256)
void prologue_kernel(const float* __restrict__ x, const float* __restrict__ qkv_w,
                     const float* __restrict__ proj_w,
                     bf16* __restrict__ xhi, bf16* __restrict__ xlo,
                     bf16* __restrict__ wqhi, bf16* __restrict__ wqlo,
                     bf16* __restrict__ wphi, bf16* __restrict__ wplo,
                     const float* __restrict__ tbl, const float* __restrict__ w1,
                     const float* __restrict__ b1, const float* __restrict__ w2,
                     const float* __restrict__ b2, float* __restrict__ tt)
{
    const int bid = blockIdx.x;
    const int tid = threadIdx.x;
    if (bid < SPLITBLK) {
        const float* in;
        bf16 *hi, *lo;
        int base;
        if (bid < XBLK)              { in = x;      hi = xhi;  lo = xlo;  base = bid; }
        else if (bid < XBLK + WQBLK) { in = qkv_w;  hi = wqhi; lo = wqlo; base = bid - XBLK; }
        else                         { in = proj_w; hi = wphi; lo = wplo; base = bid - XBLK - WQBLK; }
        const int i = base * 1024 + tid * 4;
        const float4 v = *(const float4*)(in + i);
        bf16 h0, h1, h2, h3, l0, l1, l2, l3;
        splitf(v.x, h0, l0); splitf(v.y, h1, l1);
        splitf(v.z, h2, l2); splitf(v.w, h3, l3);
        ((uint2*)hi)[i >> 2] = make_uint2(packbf(__bfloat162float(h0), __bfloat162float(h1)),
                                          packbf(__bfloat162float(h2), __bfloat162float(h3)));
        ((uint2*)lo)[i >> 2] = make_uint2(packbf(__bfloat162float(l0), __bfloat162float(l1)),
                                          packbf(__bfloat162float(l2), __bfloat162float(l3)));
        return;
    }
    // ---- CPB MLP row
    const int r = bid - SPLITBLK;
    __shared__ float hid[512];
    const float c0 = tbl[r * 2 + 0];
    const float c1 = tbl[r * 2 + 1];
    hid[tid]       = fmaxf(fmaf(c0, w1[tid * 2 + 0],
                           fmaf(c1, w1[tid * 2 + 1], b1[tid])), 0.0f);
    hid[tid + 256] = fmaxf(fmaf(c0, w1[(tid + 256) * 2 + 0],
                           fmaf(c1, w1[(tid + 256) * 2 + 1], b1[tid + 256])), 0.0f);
    __syncthreads();
    const int w = tid >> 5, lane = tid & 31;
#pragma unroll
    for (int hh = 0; hh < 2; hh++) {
        const int h = w * 2 + hh;
        float s = 0.0f;
#pragma unroll
        for (int i = 0; i < 512; i += 32)
            s = fmaf(hid[i + lane], w2[h * 512 + i + lane], s);
#pragma unroll
        for (int msk = 16; msk >= 1; msk >>= 1)
            s += __shfl_xor_sync(0xffffffffu, s, msk);
        if (lane == 0)
            tt[h * TBL + r] = s + b2[h];
    }
}

// ---------------------------------------------------------------------------
// Kernel 1: materialize permuted rb.
// rbP[h][q][blk64 + tig*16 + nt*2 + c] = log2e * tt[h][ idx[q][blk64 + nt*8 + 2tig + c] ]
// so each attn thread reads its 8 (per-row) bias pairs as contiguous 16B.
// ---------------------------------------------------------------------------
__global__ __launch_bounds__(256)
void rb_kernel(const int* __restrict__ idx, const float* __restrict__ tt,
               bf16* __restrict__ rb)
{
    const int q = blockIdx.x, h = blockIdx.y;
    const int kp = threadIdx.x * 4;            // permuted position (multiple of 4)
    const int blk = kp & ~63;
    const int j = kp & 63;
    const int tig = j >> 4;
    const int nt0 = (j & 15) >> 1;             // j%16 in {0,4,8,12} -> nt0 in {0,2,4,6}
    const int o0 = blk + nt0 * 8 + 2 * tig;
    const int o1 = blk + (nt0 + 1) * 8 + 2 * tig;
    const int2 i0 = *(const int2*)(idx + q * NTOK + o0);
    const int2 i1 = *(const int2*)(idx + q * NTOK + o1);
    const float* tth = tt + h * TBL;
    ((uint2*)rb)[(((size_t)h * NTOK + q) * NTOK + kp) >> 2] =
        make_uint2(packbf(tth[i0.x] * LOG2E, tth[i0.y] * LOG2E),
                   packbf(tth[i1.x] * LOG2E, tth[i1.y] * LOG2E));
}

// ---------------------------------------------------------------------------
// Kernel 2/4: 3xBF16 split NT-GEMM (mma.sync). 128x128 tile, k-step 32.
// MODE 0: C fp32 = A B^T + bias.   MODE 1: fused qkv norm/split epilogue.
// ---------------------------------------------------------------------------
#define GBUF 40960
#define GROW 40

template<int MODE>
__global__ __launch_bounds__(256, 2)
void gemm_bs(const bf16* __restrict__ Ahi, const bf16* __restrict__ Alo,
             const bf16* __restrict__ Bhi, const bf16* __restrict__ Blo,
             const float* __restrict__ bias, float* __restrict__ C,
             int M, int N, int K,
             const float* __restrict__ temp, const float* __restrict__ qe,
             const float* __restrict__ sls,
             bf16* __restrict__ Qhi, bf16* __restrict__ Qlo,
             bf16* __restrict__ Khi, bf16* __restrict__ Klo,
             bf16* __restrict__ Vhi, bf16* __restrict__ Vlo)
{
    extern __shared__ __align__(16) char smraw[];
    const uint32_t smb = smem_u32(smraw);

    const int tid = threadIdx.x;
    const int w = tid >> 5, lane = tid & 31;
    const int gid = lane >> 2, tig = lane & 3;
    const int wm = w >> 2, wn = w & 3;
    const int row0 = blockIdx.y * 128, col0 = blockIdx.x * 128;
    const int NS = K / 32;

    const int rowA = (lane & 7) | (lane & 8);
    const uint32_t aoff = (uint32_t)(rowA * GROW + ((lane & 16) >> 1)) * 2;
    const int rowB = (lane & 7) | ((lane & 16) >> 1);
    const uint32_t boff = (uint32_t)(rowB * GROW + (lane & 8)) * 2;

    float acc[4][4][4];
#pragma unroll
    for (int i = 0; i < 4; i++)
#pragma unroll
        for (int j = 0; j < 4; j++)
#pragma unroll
            for (int q = 0; q < 4; q++) acc[i][j][q] = 0.0f;

#define GEMM_LOAD(s, buf)                                                          \
    {                                                                              \
        const int k0_ = (s) * 32;                                                  \
        _Pragma("unroll")                                                          \
        for (int i_ = 0; i_ < 2; i_++) {                                           \
            const int slot_ = tid + i_ * 256;                                      \
            const int r_ = slot_ >> 2, q_ = slot_ & 3;                             \
            const uint32_t d_ = smb + (buf) * GBUF + (uint32_t)(r_ * 80 + q_ * 16);\
            const size_t ga_ = (size_t)(row0 + r_) * K + k0_ + q_ * 8;             \
            const size_t gb_ = (size_t)(col0 + r_) * K + k0_ + q_ * 8;             \
            cp16(d_,         Ahi + ga_);                                           \
            cp16(d_ + 10240, Alo + ga_);                                           \
            cp16(d_ + 20480, Bhi + gb_);                                           \
            cp16(d_ + 30720, Blo + gb_);                                           \
        }                                                                          \
        CP_COMMIT();                                                               \
    }

    GEMM_LOAD(0, 0);
    GEMM_LOAD(1, 1);

    for (int s = 0; s < NS; s++) {
        if (s < NS - 1) { CP_WAIT1(); } else { CP_WAIT0(); }
        __syncthreads();
        const uint32_t base = smb + (s & 1) * GBUF;
#pragma unroll
        for (int kt = 0; kt < 2; kt++) {
            unsigned bh[4][2], bl[4][2];
#pragma unroll
            for (int ntp = 0; ntp < 2; ntp++) {
                const uint32_t ba = base + 20480 + boff
                                  + (uint32_t)((wn * 32 + ntp * 16) * 80 + kt * 32);
                ldsm_x4(bh[2*ntp][0], bh[2*ntp][1], bh[2*ntp+1][0], bh[2*ntp+1][1], ba);
                ldsm_x4(bl[2*ntp][0], bl[2*ntp][1], bl[2*ntp+1][0], bl[2*ntp+1][1], ba + 10240);
            }
#pragma unroll
            for (int mt = 0; mt < 4; mt++) {
                const uint32_t aa = base + aoff
                                  + (uint32_t)((wm * 64 + mt * 16) * 80 + kt * 32);
                unsigned ah[4], al[4];
                ldsm_x4(ah[0], ah[1], ah[2], ah[3], aa);
                ldsm_x4(al[0], al[1], al[2], al[3], aa + 10240);
#pragma unroll
                for (int nt = 0; nt < 4; nt++) {
                    mma16(acc[mt][nt], ah, bh[nt][0], bh[nt][1]);
                    mma16(acc[mt][nt], al, bh[nt][0], bh[nt][1]);
                    mma16(acc[mt][nt], ah, bl[nt][0], bl[nt][1]);
                }
            }
        }
        __syncthreads();
        if (s + 2 < NS) GEMM_LOAD(s + 2, s & 1);
    }

    if (MODE == 0) {
#pragma unroll
        for (int mt = 0; mt < 4; mt++) {
            const int ra = row0 + wm * 64 + mt * 16 + gid;
#pragma unroll
            for (int nt = 0; nt < 4; nt++) {
                const int c = col0 + wn * 32 + nt * 8 + 2 * tig;
                const float bb0 = bias[c], bb1 = bias[c + 1];
                *(float2*)(C + (size_t)ra * N + c) =
                    make_float2(acc[mt][nt][0] + bb0, acc[mt][nt][1] + bb1);
                *(float2*)(C + (size_t)(ra + 8) * N + c) =
                    make_float2(acc[mt][nt][2] + bb0, acc[mt][nt][3] + bb1);
            }
        }
    } else {
        // fused qkv epilogue: warp owns 32 cols = one head slice
        const int cb = col0 + wn * 32;
        const int region = cb >> 9;                // 0:q 1:k 2:v
        const int h = (cb >> 5) & 15;
        float qscale = 0.0f;
        if (region == 0)
            qscale = log1pf(expf(temp[h])) * sls[0] * LOG2E;
        float bb[4][2];
        float qev[4][2];
#pragma unroll
        for (int nt = 0; nt < 4; nt++) {
            const int c = cb + nt * 8 + 2 * tig;
            bb[nt][0] = bias[c]; bb[nt][1] = bias[c + 1];
            if (region == 0) {
                qev[nt][0] = qe[h * HD + (c & 31)];
                qev[nt][1] = qe[h * HD + ((c + 1) & 31)];
            }
        }
        bf16* dsthi = (region == 0) ? Qhi : (region == 1) ? Khi : Vhi;
        bf16* dstlo = (region == 0) ? Qlo : (region == 1) ? Klo : Vlo;

#pragma unroll
        for (int mt = 0; mt < 4; mt++) {
#pragma unroll
            for (int half = 0; half < 2; half++) {
                const int r = row0 + wm * 64 + mt * 16 + gid + half * 8;
                const int b = r >> 10, n = r & 1023;
                float v[4][2];
                float s2 = 0.0f;
#pragma unroll
                for (int nt = 0; nt < 4; nt++) {
                    v[nt][0] = acc[mt][nt][2 * half + 0] + bb[nt][0];
                    v[nt][1] = acc[mt][nt][2 * half + 1] + bb[nt][1];
                    s2 = fmaf(v[nt][0], v[nt][0], fmaf(v[nt][1], v[nt][1], s2));
                }
                if (region < 2) {
                    s2 += __shfl_xor_sync(0xffffffffu, s2, 1);
                    s2 += __shfl_xor_sync(0xffffffffu, s2, 2);
                    const float inv = 1.0f / fmaxf(sqrtf(s2), 1e-12f);
#pragma unroll
                    for (int nt = 0; nt < 4; nt++) {
                        if (region == 0) {
                            v[nt][0] = (v[nt][0] * inv + qev[nt][0]) * qscale;
                            v[nt][1] = (v[nt][1] * inv + qev[nt][1]) * qscale;
                        } else {
                            v[nt][0] *= inv;
                            v[nt][1] *= inv;
                        }
                    }
                }
                const size_t obase = ((((size_t)b * HEADS + h) << 10) + n) * HD;
#pragma unroll
                for (int nt = 0; nt < 4; nt++) {
                    const int d = nt * 8 + 2 * tig;
                    bf16 h0, l0, h1, l1;
                    splitf(v[nt][0], h0, l0);
                    splitf(v[nt][1], h1, l1);
                    ((unsigned*)dsthi)[(obase + d) >> 1] =
                        packbf(__bfloat162float(h0), __bfloat162float(h1));
                    ((unsigned*)dstlo)[(obase + d) >> 1] =
                        packbf(__bfloat162float(l0), __bfloat162float(l1));
                }
            }
        }
    }
}

// ---------------------------------------------------------------------------
// Kernel 3: bf16-split flash attention, fixed-offset softmax, register-direct
// P fragments, fragment-major rb (4 x 16B loads per tile).
// ---------------------------------------------------------------------------
#define KROW 40
#define KPS  (64 * KROW * 2)
#define STG  (4 * KPS)
#define ATTN_SMEM (2 * STG)

__global__ __launch_bounds__(256, 2)
void attn_mma(const bf16* __restrict__ Qhi_, const bf16* __restrict__ Qlo_,
              const bf16* __restrict__ Khi_, const bf16* __restrict__ Klo_,
              const bf16* __restrict__ Vhi_, const bf16* __restrict__ Vlo_,
              const bf16* __restrict__ rb, bf16* __restrict__ outhi,
              bf16* __restrict__ outlo)
{
    extern __shared__ __align__(16) char smraw[];
    const uint32_t smb = smem_u32(smraw);

    const int tid = threadIdx.x;
    const int w = tid >> 5, lane = tid & 31;
    const int gid = lane >> 2, tig = lane & 3;
    const int b = blockIdx.x, h = blockIdx.y, q0 = blockIdx.z * 128;
    const size_t bh = ((size_t)b * HEADS + h) * NTOK * HD;
    const bf16* Khg = Khi_ + bh;
    const bf16* Klg = Klo_ + bh;
    const bf16* Vhg = Vhi_ + bh;
    const bf16* Vlg = Vlo_ + bh;
    const bf16* rbh = rb + (size_t)h * NTOK * NTOK;
    const int r0 = q0 + w * 16 + gid;
    const int r1 = r0 + 8;

    const uint32_t koff = (uint32_t)((((lane & 7) | ((lane & 16) >> 1)) * KROW + (lane & 8)) * 2);
    const uint32_t voff = (uint32_t)((((lane & 7) | (lane & 8)) * KROW + ((lane & 16) >> 1)) * 2);

    unsigned qh[2][4], ql[2][4];
#pragma unroll
    for (int kt = 0; kt < 2; kt++) {
        const int d0 = kt * 16 + 2 * tig;
        qh[kt][0] = *(const unsigned*)(Qhi_ + bh + (size_t)r0 * HD + d0);
        qh[kt][1] = *(const unsigned*)(Qhi_ + bh + (size_t)r1 * HD + d0);
        qh[kt][2] = *(const unsigned*)(Qhi_ + bh + (size_t)r0 * HD + d0 + 8);
        qh[kt][3] = *(const unsigned*)(Qhi_ + bh + (size_t)r1 * HD + d0 + 8);
        ql[kt][0] = *(const unsigned*)(Qlo_ + bh + (size_t)r0 * HD + d0);
        ql[kt][1] = *(const unsigned*)(Qlo_ + bh + (size_t)r1 * HD + d0);
        ql[kt][2] = *(const unsigned*)(Qlo_ + bh + (size_t)r0 * HD + d0 + 8);
        ql[kt][3] = *(const unsigned*)(Qlo_ + bh + (size_t)r1 * HD + d0 + 8);
    }

    float o[4][4];
#pragma unroll
    for (int i = 0; i < 4; i++)
#pragma unroll
        for (int j = 0; j < 4; j++) o[i][j] = 0.0f;
    float l0 = 0.0f, l1 = 0.0f;

#define ATTN_LOAD(t, buf)                                                      \
    {                                                                          \
        const int r_ = tid >> 2, q_ = tid & 3;                                 \
        const uint32_t d_ = smb + (buf) * STG + (uint32_t)(r_ * 80 + q_ * 16); \
        const size_t g_ = (size_t)((t) * 64 + r_) * HD + q_ * 8;               \
        cp16(d_,           Khg + g_);                                          \
        cp16(d_ + KPS,     Klg + g_);                                          \
        cp16(d_ + 2 * KPS, Vhg + g_);                                          \
        cp16(d_ + 3 * KPS, Vlg + g_);                                          \
        CP_COMMIT();                                                           \
    }

    ATTN_LOAD(0, 0);

    for (int t = 0; t < 16; t++) {
        if (t < 15) ATTN_LOAD(t + 1, (t + 1) & 1);
        const int key0 = t * 64;

        // gathered bias (fragment-major): 4 x 16B loads cover the whole tile
        float s[8][4];
        {
            const bf16* rp0 = rbh + ((size_t)r0 << 10) + key0 + tig * 16;
            const bf16* rp1 = rbh + ((size_t)r1 << 10) + key0 + tig * 16;
            const uint4 Ua = *(const uint4*)rp0;
            const uint4 Ub = *(const uint4*)(rp0 + 8);
            const uint4 Uc = *(const uint4*)rp1;
            const uint4 Ud = *(const uint4*)(rp1 + 8);
            const unsigned pr0[8] = {Ua.x, Ua.y, Ua.z, Ua.w, Ub.x, Ub.y, Ub.z, Ub.w};
            const unsigned pr1[8] = {Uc.x, Uc.y, Uc.z, Uc.w, Ud.x, Ud.y, Ud.z, Ud.w};
#pragma unroll
            for (int nt = 0; nt < 8; nt++) {
                const float2 f0 = __bfloat1622float2(*(const __nv_bfloat162*)&pr0[nt]);
                const float2 f1 = __bfloat1622float2(*(const __nv_bfloat162*)&pr1[nt]);
                s[nt][0] = f0.x; s[nt][1] = f0.y; s[nt][2] = f1.x; s[nt][3] = f1.y;
            }
        }

        if (t < 15) { CP_WAIT1(); } else { CP_WAIT0(); }
        __syncthreads();
        const uint32_t base = smb + (t & 1) * STG;

        // ---- S += Q K^T (3xBF16)
#pragma unroll
        for (int kt = 0; kt < 2; kt++) {
#pragma unroll
            for (int ntp = 0; ntp < 4; ntp++) {
                const uint32_t ka = base + koff + (uint32_t)(ntp * 1280 + kt * 32);
                unsigned kh0, kh1, kh2, kh3, kl0, kl1, kl2, kl3;
                ldsm_x4(kh0, kh1, kh2, kh3, ka);
                ldsm_x4(kl0, kl1, kl2, kl3, ka + KPS);
                mma16(s[2*ntp],   qh[kt], kh0, kh1);
                mma16(s[2*ntp],   ql[kt], kh0, kh1);
                mma16(s[2*ntp],   qh[kt], kl0, kl1);
                mma16(s[2*ntp+1], qh[kt], kh2, kh3);
                mma16(s[2*ntp+1], ql[kt], kh2, kh3);
                mma16(s[2*ntp+1], qh[kt], kl2, kl3);
            }
        }

        // ---- fixed-offset softmax
#pragma unroll
        for (int nt = 0; nt < 8; nt++) {
            s[nt][0] = ex2(s[nt][0] - SMSHIFT);
            s[nt][1] = ex2(s[nt][1] - SMSHIFT);
            s[nt][2] = ex2(s[nt][2] - SMSHIFT);
            s[nt][3] = ex2(s[nt][3] - SMSHIFT);
            l0 += s[nt][0] + s[nt][1];
            l1 += s[nt][2] + s[nt][3];
        }

        // ---- O += P V, register-direct P fragments
#pragma unroll
        for (int kt = 0; kt < 4; kt++) {
            unsigned ph[4], pl[4];
#pragma unroll
            for (int half = 0; half < 2; half++) {
                const int nt = 2 * kt + half;
                const unsigned h01 = packbf(s[nt][0], s[nt][1]);
                const unsigned h23 = packbf(s[nt][2], s[nt][3]);
                const float2 f01 = __bfloat1622float2(*(const __nv_bfloat162*)&h01);
                const float2 f23 = __bfloat1622float2(*(const __nv_bfloat162*)&h23);
                ph[2 * half + 0] = h01;
                ph[2 * half + 1] = h23;
                pl[2 * half + 0] = packbf(s[nt][0] - f01.x, s[nt][1] - f01.y);
                pl[2 * half + 1] = packbf(s[nt][2] - f23.x, s[nt][3] - f23.y);
            }
#pragma unroll
            for (int ntp = 0; ntp < 2; ntp++) {
                const uint32_t va = base + 2 * KPS + voff + (uint32_t)(kt * 1280 + ntp * 32);
                unsigned vh0, vh1, vh2, vh3, vl0, vl1, vl2, vl3;
                ldsm_x4t(vh0, vh1, vh2, vh3, va);
                ldsm_x4t(vl0, vl1, vl2, vl3, va + KPS);
                mma16(o[2*ntp],   ph, vh0, vh1);
                mma16(o[2*ntp],   pl, vh0, vh1);
                mma16(o[2*ntp],   ph, vl0, vl1);
                mma16(o[2*ntp+1], ph, vh2, vh3);
                mma16(o[2*ntp+1], pl, vh2, vh3);
                mma16(o[2*ntp+1], ph, vl2, vl3);
            }
        }
        __syncthreads();
    }

    l0 += __shfl_xor_sync(0xffffffffu, l0, 1);
    l0 += __shfl_xor_sync(0xffffffffu, l0, 2);
    l1 += __shfl_xor_sync(0xffffffffu, l1, 1);
    l1 += __shfl_xor_sync(0xffffffffu, l1, 2);

    const float inv0 = 1.0f / l0, inv1 = 1.0f / l1;
#pragma unroll
    for (int dnt = 0; dnt < 4; dnt++) {
        const int c = h * HD + dnt * 8 + 2 * tig;
        {
            const float v0 = o[dnt][0] * inv0, v1 = o[dnt][1] * inv0;
            const float h0 = __bfloat162float(__float2bfloat16_rn(v0));
            const float h1 = __bfloat162float(__float2bfloat16_rn(v1));
            const size_t u = ((size_t)(((size_t)b << 10) + r0) * DIM + c) >> 1;
            ((unsigned*)outhi)[u] = packbf(v0, v1);
            ((unsigned*)outlo)[u] = packbf(v0 - h0, v1 - h1);
        }
        {
            const float v0 = o[dnt][2] * inv1, v1 = o[dnt][3] * inv1;
            const float h0 = __bfloat162float(__float2bfloat16_rn(v0));
            const float h1 = __bfloat162float(__float2bfloat16_rn(v1));
            const size_t u = ((size_t)(((size_t)b << 10) + r1) * DIM + c) >> 1;
            ((unsigned*)outhi)[u] = packbf(v0, v1);
            ((unsigned*)outlo)[u] = packbf(v0 - h0, v1 - h1);
        }
    }
}

// ---------------------------------------------------------------------------
extern "C" void kernel_launch(void* const* d_in, const int* in_sizes, int n_in,
                              void* d_out, int out_size)
{
    (void)in_sizes; (void)n_in; (void)out_size;
    const float* x      = (const float*)d_in[0];
    const float* qkv_w  = (const float*)d_in[1];
    const float* qkv_b  = (const float*)d_in[2];
    const float* proj_w = (const float*)d_in[3];
    const float* proj_b = (const float*)d_in[4];
    const float* temp   = (const float*)d_in[5];
    const float* qe     = (const float*)d_in[6];
    const float* c1w    = (const float*)d_in[7];
    const float* c1b    = (const float*)d_in[8];
    const float* c2w    = (const float*)d_in[9];
    const float* c2b    = (const float*)d_in[10];
    const float* rct    = (const float*)d_in[11];
    const int*   rpi    = (const int*)d_in[12];
    const float* sls    = (const float*)d_in[13];
    float* out = (float*)d_out;

    float *tt_s;
    bf16 *xhi, *xlo, *wqhi, *wqlo, *wphi, *wplo;
    bf16 *Qhi, *Qlo, *Khi, *Klo, *Vhi, *Vlo, *ahi, *alo, *rb_s;
    cudaGetSymbolAddress((void**)&tt_s,  g_tt);
    cudaGetSymbolAddress((void**)&xhi,  g_xhi);  cudaGetSymbolAddress((void**)&xlo,  g_xlo);
    cudaGetSymbolAddress((void**)&wqhi, g_wqhi); cudaGetSymbolAddress((void**)&wqlo, g_wqlo);
    cudaGetSymbolAddress((void**)&wphi, g_wphi); cudaGetSymbolAddress((void**)&wplo, g_wplo);
    cudaGetSymbolAddress((void**)&Qhi,  g_Qhi);  cudaGetSymbolAddress((void**)&Qlo,  g_Qlo);
    cudaGetSymbolAddress((void**)&Khi,  g_Khi);  cudaGetSymbolAddress((void**)&Klo,  g_Klo);
    cudaGetSymbolAddress((void**)&Vhi,  g_Vhi);  cudaGetSymbolAddress((void**)&Vlo,  g_Vlo);
    cudaGetSymbolAddress((void**)&ahi,  g_ahi);  cudaGetSymbolAddress((void**)&alo,  g_alo);
    cudaGetSymbolAddress((void**)&rb_s, g_rb);

    cudaFuncSetAttribute(attn_mma, cudaFuncAttributeMaxDynamicSharedMemorySize, ATTN_SMEM);
    cudaFuncSetAttribute(gemm_bs<0>, cudaFuncAttributeMaxDynamicSharedMemorySize, 2 * GBUF);
    cudaFuncSetAttribute(gemm_bs<1>, cudaFuncAttributeMaxDynamicSharedMemorySize, 2 * GBUF);

    // 0. fused prologue: splits + CPB MLP
    prologue_kernel<<<SPLITBLK + TBL, 256>>>(
        x, qkv_w, proj_w, xhi, xlo, wqhi, wqlo, wphi, wplo,
        rct, c1w, c1b, c2w, c2b, tt_s);

    // 1. permuted bias materialization
    rb_kernel<<<dim3(NTOK, HEADS), 256>>>(rpi, tt_s, rb_s);

    // 2. qkv projection with fused norm/split epilogue
    gemm_bs<1><<<dim3(12, 64), 256, 2 * GBUF>>>(
        xhi, xlo, wqhi, wqlo, qkv_b, nullptr, B_ * NTOK, 3 * DIM, DIM,
        temp, qe, sls, Qhi, Qlo, Khi, Klo, Vhi, Vlo);

    // 3. fused attention (batch fastest for rb L2 reuse)
    attn_mma<<<dim3(B_, HEADS, NTOK / 128), 256, ATTN_SMEM>>>(
        Qhi, Qlo, Khi, Klo, Vhi, Vlo, rb_s, ahi, alo);

    // 4. output projection -> fp32 out
    gemm_bs<0><<<dim3(4, 64), 256, 2 * GBUF>>>(
        ahi, alo, wphi, wplo, proj_b, out, B_ * NTOK, DIM, DIM,
        nullptr, nullptr, nullptr,
        nullptr, nullptr, nullptr, nullptr, nullptr, nullptr);
}

// round 8
// speedup vs baseline: 3.2272x; 1.0296x over previous
#include <cuda_runtime.h>
#include <cuda_bf16.h>
#include <cstdint>
#include <math.h>
#include <math_constants.h>

#define B_     8
#define NTOK   1024
#define DIM    512
#define HEADS  16
#define HD     32
#define TBL    3969
#define LOG2E  1.4426950408889634f
#define SMSHIFT 48.0f

typedef __nv_bfloat16 bf16;

// ---------------- scratch (device globals; no dynamic allocation) ----------
__device__ bf16  g_xhi[B_ * NTOK * DIM],        g_xlo[B_ * NTOK * DIM];
__device__ bf16  g_wqhi[3 * DIM * DIM],         g_wqlo[3 * DIM * DIM];
__device__ bf16  g_wphi[DIM * DIM],             g_wplo[DIM * DIM];
__device__ bf16  g_Qhi[B_ * HEADS * NTOK * HD], g_Qlo[B_ * HEADS * NTOK * HD];
__device__ bf16  g_Khi[B_ * HEADS * NTOK * HD], g_Klo[B_ * HEADS * NTOK * HD];
__device__ bf16  g_Vhi[B_ * HEADS * NTOK * HD], g_Vlo[B_ * HEADS * NTOK * HD];
__device__ bf16  g_ahi[B_ * NTOK * DIM],        g_alo[B_ * NTOK * DIM];
__device__ bf16  g_rb [HEADS * NTOK * NTOK];    // bias * log2e, fragment-major permuted
__device__ float g_tt [HEADS * TBL];

// ---------------------------------------------------------------------------
// helpers
// ---------------------------------------------------------------------------
__device__ __forceinline__ void mma16(float* d, const unsigned* a, unsigned b0, unsigned b1) {
    asm volatile("mma.sync.aligned.m16n8k16.row.col.f32.bf16.bf16.f32 "
                 "{%0,%1,%2,%3}, {%4,%5,%6,%7}, {%8,%9}, {%0,%1,%2,%3};"
                 : "+f"(d[0]), "+f"(d[1]), "+f"(d[2]), "+f"(d[3])
                 : "r"(a[0]), "r"(a[1]), "r"(a[2]), "r"(a[3]), "r"(b0), "r"(b1));
}
__device__ __forceinline__ void ldsm_x4(unsigned& r0, unsigned& r1, unsigned& r2,
                                        unsigned& r3, unsigned addr) {
    asm volatile("ldmatrix.sync.aligned.m8n8.x4.shared.b16 {%0,%1,%2,%3}, [%4];"
                 : "=r"(r0), "=r"(r1), "=r"(r2), "=r"(r3) : "r"(addr));
}
__device__ __forceinline__ void ldsm_x4t(unsigned& r0, unsigned& r1, unsigned& r2,
                                         unsigned& r3, unsigned addr) {
    asm volatile("ldmatrix.sync.aligned.m8n8.x4.trans.shared.b16 {%0,%1,%2,%3}, [%4];"
                 : "=r"(r0), "=r"(r1), "=r"(r2), "=r"(r3) : "r"(addr));
}
__device__ __forceinline__ void cp16(uint32_t dst, const void* src) {
    asm volatile("cp.async.cg.shared.global [%0], [%1], 16;" :: "r"(dst), "l"(src));
}
#define CP_COMMIT() asm volatile("cp.async.commit_group;" ::: "memory")
#define CP_WAIT1()  asm volatile("cp.async.wait_group 1;" ::: "memory")
#define CP_WAIT0()  asm volatile("cp.async.wait_group 0;" ::: "memory")

__device__ __forceinline__ unsigned packbf(float a, float b) {
    __nv_bfloat162 h = __floats2bfloat162_rn(a, b);
    return *(unsigned*)&h;
}
__device__ __forceinline__ void splitf(float x, bf16& hi, bf16& lo) {
    hi = __float2bfloat16_rn(x);
    lo = __float2bfloat16_rn(x - __bfloat162float(hi));
}
__device__ __forceinline__ float ex2(float x) {
    float r;
    asm("ex2.approx.ftz.f32 %0, %1;" : "=f"(r) : "f"(x));
    return r;
}
__device__ __forceinline__ uint32_t smem_u32(const void* p) {
    return (uint32_t)__cvta_generic_to_shared(p);
}

// ---------------------------------------------------------------------------
// Kernel 0: fused prologue — three fp32->bf16 hi/lo splits + CPB MLP.
// ---------------------------------------------------------------------------
#define XELEM  (B_ * NTOK * DIM)
#define WQELEM (3 * DIM * DIM)
#define WPELEM (DIM * DIM)
#define XBLK   (XELEM / 1024)
#define WQBLK  (WQELEM / 1024)
#define WPBLK  (WPELEM / 1024)
#define SPLITBLK (XBLK + WQBLK + WPBLK)

__global__ __launch_bounds__(256)
void prologue_kernel(const float* __restrict__ x, const float* __restrict__ qkv_w,
                     const float* __restrict__ proj_w,
                     bf16* __restrict__ xhi, bf16* __restrict__ xlo,
                     bf16* __restrict__ wqhi, bf16* __restrict__ wqlo,
                     bf16* __restrict__ wphi, bf16* __restrict__ wplo,
                     const float* __restrict__ tbl, const float* __restrict__ w1,
                     const float* __restrict__ b1, const float* __restrict__ w2,
                     const float* __restrict__ b2, float* __restrict__ tt)
{
    const int bid = blockIdx.x;
    const int tid = threadIdx.x;
    if (bid < SPLITBLK) {
        const float* in;
        bf16 *hi, *lo;
        int base;
        if (bid < XBLK)              { in = x;      hi = xhi;  lo = xlo;  base = bid; }
        else if (bid < XBLK + WQBLK) { in = qkv_w;  hi = wqhi; lo = wqlo; base = bid - XBLK; }
        else                         { in = proj_w; hi = wphi; lo = wplo; base = bid - XBLK - WQBLK; }
        const int i = base * 1024 + tid * 4;
        const float4 v = *(const float4*)(in + i);
        bf16 h0, h1, h2, h3, l0, l1, l2, l3;
        splitf(v.x, h0, l0); splitf(v.y, h1, l1);
        splitf(v.z, h2, l2); splitf(v.w, h3, l3);
        ((uint2*)hi)[i >> 2] = make_uint2(packbf(__bfloat162float(h0), __bfloat162float(h1)),
                                          packbf(__bfloat162float(h2), __bfloat162float(h3)));
        ((uint2*)lo)[i >> 2] = make_uint2(packbf(__bfloat162float(l0), __bfloat162float(l1)),
                                          packbf(__bfloat162float(l2), __bfloat162float(l3)));
        return;
    }
    const int r = bid - SPLITBLK;
    __shared__ float hid[512];
    const float c0 = tbl[r * 2 + 0];
    const float c1 = tbl[r * 2 + 1];
    hid[tid]       = fmaxf(fmaf(c0, w1[tid * 2 + 0],
                           fmaf(c1, w1[tid * 2 + 1], b1[tid])), 0.0f);
    hid[tid + 256] = fmaxf(fmaf(c0, w1[(tid + 256) * 2 + 0],
                           fmaf(c1, w1[(tid + 256) * 2 + 1], b1[tid + 256])), 0.0f);
    __syncthreads();
    const int w = tid >> 5, lane = tid & 31;
#pragma unroll
    for (int hh = 0; hh < 2; hh++) {
        const int h = w * 2 + hh;
        float s = 0.0f;
#pragma unroll
        for (int i = 0; i < 512; i += 32)
            s = fmaf(hid[i + lane], w2[h * 512 + i + lane], s);
#pragma unroll
        for (int msk = 16; msk >= 1; msk >>= 1)
            s += __shfl_xor_sync(0xffffffffu, s, msk);
        if (lane == 0)
            tt[h * TBL + r] = s + b2[h];
    }
}

// ---------------------------------------------------------------------------
// Kernel 1/3: 3xBF16 split NT-GEMM (mma.sync). 128x128 tile, k-step 32.
// MODE 0: C fp32 = A B^T + bias.
// MODE 1: fused qkv norm/split epilogue + TRAILING RB BLOCKS: blocks with
//         blockIdx.y >= M/128 materialize permuted rb (one q-row, all heads),
//         scheduled after gemm blocks -> fill the gemm's wave tail.
// ---------------------------------------------------------------------------
#define GBUF 40960
#define GROW 40
#define RB_YBASE 64     // = M/128 for the qkv gemm

template<int MODE>
__global__ __launch_bounds__(256, 2)
void gemm_bs(const bf16* __restrict__ Ahi, const bf16* __restrict__ Alo,
             const bf16* __restrict__ Bhi, const bf16* __restrict__ Blo,
             const float* __restrict__ bias, float* __restrict__ C,
             int M, int N, int K,
             const float* __restrict__ temp, const float* __restrict__ qe,
             const float* __restrict__ sls,
             bf16* __restrict__ Qhi, bf16* __restrict__ Qlo,
             bf16* __restrict__ Khi, bf16* __restrict__ Klo,
             bf16* __restrict__ Vhi, bf16* __restrict__ Vlo,
             const int* __restrict__ idx, const float* __restrict__ tt,
             bf16* __restrict__ rbout)
{
    extern __shared__ __align__(16) char smraw[];
    const uint32_t smb = smem_u32(smraw);
    const int tid = threadIdx.x;

    if (MODE == 1 && blockIdx.y >= RB_YBASE) {
        // ---------------- rb materialization path ----------------
        const int q = (blockIdx.y - RB_YBASE) * 12 + blockIdx.x;
        if (q >= NTOK) return;
        int* idxbuf = (int*)smraw;
        ((int4*)idxbuf)[tid] = ((const int4*)(idx + q * NTOK))[tid];
        __syncthreads();
        const int kp = tid * 4;
        const int blk = kp & ~63;
        const int j = kp & 63;
        const int tig = j >> 4;
        const int nt0 = (j & 15) >> 1;
        const int2 i0 = *(const int2*)&idxbuf[blk + nt0 * 8 + 2 * tig];
        const int2 i1 = *(const int2*)&idxbuf[blk + (nt0 + 1) * 8 + 2 * tig];
#pragma unroll 4
        for (int h = 0; h < HEADS; h++) {
            const float* tth = tt + h * TBL;
            ((uint2*)rbout)[(((size_t)h * NTOK + q) * NTOK + kp) >> 2] =
                make_uint2(packbf(tth[i0.x] * LOG2E, tth[i0.y] * LOG2E),
                           packbf(tth[i1.x] * LOG2E, tth[i1.y] * LOG2E));
        }
        return;
    }

    // ---------------- gemm path ----------------
    const int w = tid >> 5, lane = tid & 31;
    const int gid = lane >> 2, tig = lane & 3;
    const int wm = w >> 2, wn = w & 3;
    const int row0 = blockIdx.y * 128, col0 = blockIdx.x * 128;
    const int NS = K / 32;

    const int rowA = (lane & 7) | (lane & 8);
    const uint32_t aoff = (uint32_t)(rowA * GROW + ((lane & 16) >> 1)) * 2;
    const int rowB = (lane & 7) | ((lane & 16) >> 1);
    const uint32_t boff = (uint32_t)(rowB * GROW + (lane & 8)) * 2;

    float acc[4][4][4];
#pragma unroll
    for (int i = 0; i < 4; i++)
#pragma unroll
        for (int j = 0; j < 4; j++)
#pragma unroll
            for (int q = 0; q < 4; q++) acc[i][j][q] = 0.0f;

#define GEMM_LOAD(s, buf)                                                          \
    {                                                                              \
        const int k0_ = (s) * 32;                                                  \
        _Pragma("unroll")                                                          \
        for (int i_ = 0; i_ < 2; i_++) {                                           \
            const int slot_ = tid + i_ * 256;                                      \
            const int r_ = slot_ >> 2, q_ = slot_ & 3;                             \
            const uint32_t d_ = smb + (buf) * GBUF + (uint32_t)(r_ * 80 + q_ * 16);\
            const size_t ga_ = (size_t)(row0 + r_) * K + k0_ + q_ * 8;             \
            const size_t gb_ = (size_t)(col0 + r_) * K + k0_ + q_ * 8;             \
            cp16(d_,         Ahi + ga_);                                           \
            cp16(d_ + 10240, Alo + ga_);                                           \
            cp16(d_ + 20480, Bhi + gb_);                                           \
            cp16(d_ + 30720, Blo + gb_);                                           \
        }                                                                          \
        CP_COMMIT();                                                               \
    }

    GEMM_LOAD(0, 0);
    GEMM_LOAD(1, 1);

    for (int s = 0; s < NS; s++) {
        if (s < NS - 1) { CP_WAIT1(); } else { CP_WAIT0(); }
        __syncthreads();
        const uint32_t base = smb + (s & 1) * GBUF;
#pragma unroll
        for (int kt = 0; kt < 2; kt++) {
            unsigned bh[4][2], bl[4][2];
#pragma unroll
            for (int ntp = 0; ntp < 2; ntp++) {
                const uint32_t ba = base + 20480 + boff
                                  + (uint32_t)((wn * 32 + ntp * 16) * 80 + kt * 32);
                ldsm_x4(bh[2*ntp][0], bh[2*ntp][1], bh[2*ntp+1][0], bh[2*ntp+1][1], ba);
                ldsm_x4(bl[2*ntp][0], bl[2*ntp][1], bl[2*ntp+1][0], bl[2*ntp+1][1], ba + 10240);
            }
#pragma unroll
            for (int mt = 0; mt < 4; mt++) {
                const uint32_t aa = base + aoff
                                  + (uint32_t)((wm * 64 + mt * 16) * 80 + kt * 32);
                unsigned ah[4], al[4];
                ldsm_x4(ah[0], ah[1], ah[2], ah[3], aa);
                ldsm_x4(al[0], al[1], al[2], al[3], aa + 10240);
#pragma unroll
                for (int nt = 0; nt < 4; nt++) {
                    mma16(acc[mt][nt], ah, bh[nt][0], bh[nt][1]);
                    mma16(acc[mt][nt], al, bh[nt][0], bh[nt][1]);
                    mma16(acc[mt][nt], ah, bl[nt][0], bl[nt][1]);
                }
            }
        }
        __syncthreads();
        if (s + 2 < NS) GEMM_LOAD(s + 2, s & 1);
    }

    if (MODE == 0) {
#pragma unroll
        for (int mt = 0; mt < 4; mt++) {
            const int ra = row0 + wm * 64 + mt * 16 + gid;
#pragma unroll
            for (int nt = 0; nt < 4; nt++) {
                const int c = col0 + wn * 32 + nt * 8 + 2 * tig;
                const float bb0 = bias[c], bb1 = bias[c + 1];
                *(float2*)(C + (size_t)ra * N + c) =
                    make_float2(acc[mt][nt][0] + bb0, acc[mt][nt][1] + bb1);
                *(float2*)(C + (size_t)(ra + 8) * N + c) =
                    make_float2(acc[mt][nt][2] + bb0, acc[mt][nt][3] + bb1);
            }
        }
    } else {
        const int cb = col0 + wn * 32;
        const int region = cb >> 9;                // 0:q 1:k 2:v
        const int h = (cb >> 5) & 15;
        float qscale = 0.0f;
        if (region == 0)
            qscale = log1pf(expf(temp[h])) * sls[0] * LOG2E;
        float bb[4][2];
        float qev[4][2];
#pragma unroll
        for (int nt = 0; nt < 4; nt++) {
            const int c = cb + nt * 8 + 2 * tig;
            bb[nt][0] = bias[c]; bb[nt][1] = bias[c + 1];
            if (region == 0) {
                qev[nt][0] = qe[h * HD + (c & 31)];
                qev[nt][1] = qe[h * HD + ((c + 1) & 31)];
            }
        }
        bf16* dsthi = (region == 0) ? Qhi : (region == 1) ? Khi : Vhi;
        bf16* dstlo = (region == 0) ? Qlo : (region == 1) ? Klo : Vlo;

#pragma unroll
        for (int mt = 0; mt < 4; mt++) {
#pragma unroll
            for (int half = 0; half < 2; half++) {
                const int r = row0 + wm * 64 + mt * 16 + gid + half * 8;
                const int b = r >> 10, n = r & 1023;
                float v[4][2];
                float s2 = 0.0f;
#pragma unroll
                for (int nt = 0; nt < 4; nt++) {
                    v[nt][0] = acc[mt][nt][2 * half + 0] + bb[nt][0];
                    v[nt][1] = acc[mt][nt][2 * half + 1] + bb[nt][1];
                    s2 = fmaf(v[nt][0], v[nt][0], fmaf(v[nt][1], v[nt][1], s2));
                }
                if (region < 2) {
                    s2 += __shfl_xor_sync(0xffffffffu, s2, 1);
                    s2 += __shfl_xor_sync(0xffffffffu, s2, 2);
                    const float inv = 1.0f / fmaxf(sqrtf(s2), 1e-12f);
#pragma unroll
                    for (int nt = 0; nt < 4; nt++) {
                        if (region == 0) {
                            v[nt][0] = (v[nt][0] * inv + qev[nt][0]) * qscale;
                            v[nt][1] = (v[nt][1] * inv + qev[nt][1]) * qscale;
                        } else {
                            v[nt][0] *= inv;
                            v[nt][1] *= inv;
                        }
                    }
                }
                const size_t obase = ((((size_t)b * HEADS + h) << 10) + n) * HD;
#pragma unroll
                for (int nt = 0; nt < 4; nt++) {
                    const int d = nt * 8 + 2 * tig;
                    bf16 h0, l0, h1, l1;
                    splitf(v[nt][0], h0, l0);
                    splitf(v[nt][1], h1, l1);
                    ((unsigned*)dsthi)[(obase + d) >> 1] =
                        packbf(__bfloat162float(h0), __bfloat162float(h1));
                    ((unsigned*)dstlo)[(obase + d) >> 1] =
                        packbf(__bfloat162float(l0), __bfloat162float(l1));
                }
            }
        }
    }
}

// ---------------------------------------------------------------------------
// Kernel 2: bf16-split flash attention, fixed-offset softmax, register-direct
// P fragments, fragment-major rb. V ldsm issued BEFORE P packing per kt.
// ---------------------------------------------------------------------------
#define KROW 40
#define KPS  (64 * KROW * 2)
#define STG  (4 * KPS)
#define ATTN_SMEM (2 * STG)

__global__ __launch_bounds__(256, 2)
void attn_mma(const bf16* __restrict__ Qhi_, const bf16* __restrict__ Qlo_,
              const bf16* __restrict__ Khi_, const bf16* __restrict__ Klo_,
              const bf16* __restrict__ Vhi_, const bf16* __restrict__ Vlo_,
              const bf16* __restrict__ rb, bf16* __restrict__ outhi,
              bf16* __restrict__ outlo)
{
    extern __shared__ __align__(16) char smraw[];
    const uint32_t smb = smem_u32(smraw);

    const int tid = threadIdx.x;
    const int w = tid >> 5, lane = tid & 31;
    const int gid = lane >> 2, tig = lane & 3;
    const int b = blockIdx.x, h = blockIdx.y, q0 = blockIdx.z * 128;
    const size_t bh = ((size_t)b * HEADS + h) * NTOK * HD;
    const bf16* Khg = Khi_ + bh;
    const bf16* Klg = Klo_ + bh;
    const bf16* Vhg = Vhi_ + bh;
    const bf16* Vlg = Vlo_ + bh;
    const bf16* rbh = rb + (size_t)h * NTOK * NTOK;
    const int r0 = q0 + w * 16 + gid;
    const int r1 = r0 + 8;

    const uint32_t koff = (uint32_t)((((lane & 7) | ((lane & 16) >> 1)) * KROW + (lane & 8)) * 2);
    const uint32_t voff = (uint32_t)((((lane & 7) | (lane & 8)) * KROW + ((lane & 16) >> 1)) * 2);

    unsigned qh[2][4], ql[2][4];
#pragma unroll
    for (int kt = 0; kt < 2; kt++) {
        const int d0 = kt * 16 + 2 * tig;
        qh[kt][0] = *(const unsigned*)(Qhi_ + bh + (size_t)r0 * HD + d0);
        qh[kt][1] = *(const unsigned*)(Qhi_ + bh + (size_t)r1 * HD + d0);
        qh[kt][2] = *(const unsigned*)(Qhi_ + bh + (size_t)r0 * HD + d0 + 8);
        qh[kt][3] = *(const unsigned*)(Qhi_ + bh + (size_t)r1 * HD + d0 + 8);
        ql[kt][0] = *(const unsigned*)(Qlo_ + bh + (size_t)r0 * HD + d0);
        ql[kt][1] = *(const unsigned*)(Qlo_ + bh + (size_t)r1 * HD + d0);
        ql[kt][2] = *(const unsigned*)(Qlo_ + bh + (size_t)r0 * HD + d0 + 8);
        ql[kt][3] = *(const unsigned*)(Qlo_ + bh + (size_t)r1 * HD + d0 + 8);
    }

    float o[4][4];
#pragma unroll
    for (int i = 0; i < 4; i++)
#pragma unroll
        for (int j = 0; j < 4; j++) o[i][j] = 0.0f;
    float l0 = 0.0f, l1 = 0.0f;

#define ATTN_LOAD(t, buf)                                                      \
    {                                                                          \
        const int r_ = tid >> 2, q_ = tid & 3;                                 \
        const uint32_t d_ = smb + (buf) * STG + (uint32_t)(r_ * 80 + q_ * 16); \
        const size_t g_ = (size_t)((t) * 64 + r_) * HD + q_ * 8;               \
        cp16(d_,           Khg + g_);                                          \
        cp16(d_ + KPS,     Klg + g_);                                          \
        cp16(d_ + 2 * KPS, Vhg + g_);                                          \
        cp16(d_ + 3 * KPS, Vlg + g_);                                          \
        CP_COMMIT();                                                           \
    }

    ATTN_LOAD(0, 0);

    for (int t = 0; t < 16; t++) {
        if (t < 15) ATTN_LOAD(t + 1, (t + 1) & 1);
        const int key0 = t * 64;

        // gathered bias (fragment-major): 4 x 16B loads cover the whole tile
        float s[8][4];
        {
            const bf16* rp0 = rbh + ((size_t)r0 << 10) + key0 + tig * 16;
            const bf16* rp1 = rbh + ((size_t)r1 << 10) + key0 + tig * 16;
            const uint4 Ua = *(const uint4*)rp0;
            const uint4 Ub = *(const uint4*)(rp0 + 8);
            const uint4 Uc = *(const uint4*)rp1;
            const uint4 Ud = *(const uint4*)(rp1 + 8);
            const unsigned pr0[8] = {Ua.x, Ua.y, Ua.z, Ua.w, Ub.x, Ub.y, Ub.z, Ub.w};
            const unsigned pr1[8] = {Uc.x, Uc.y, Uc.z, Uc.w, Ud.x, Ud.y, Ud.z, Ud.w};
#pragma unroll
            for (int nt = 0; nt < 8; nt++) {
                const float2 f0 = __bfloat1622float2(*(const __nv_bfloat162*)&pr0[nt]);
                const float2 f1 = __bfloat1622float2(*(const __nv_bfloat162*)&pr1[nt]);
                s[nt][0] = f0.x; s[nt][1] = f0.y; s[nt][2] = f1.x; s[nt][3] = f1.y;
            }
        }

        if (t < 15) { CP_WAIT1(); } else { CP_WAIT0(); }
        __syncthreads();
        const uint32_t base = smb + (t & 1) * STG;

        // ---- S += Q K^T (3xBF16)
#pragma unroll
        for (int kt = 0; kt < 2; kt++) {
#pragma unroll
            for (int ntp = 0; ntp < 4; ntp++) {
                const uint32_t ka = base + koff + (uint32_t)(ntp * 1280 + kt * 32);
                unsigned kh0, kh1, kh2, kh3, kl0, kl1, kl2, kl3;
                ldsm_x4(kh0, kh1, kh2, kh3, ka);
                ldsm_x4(kl0, kl1, kl2, kl3, ka + KPS);
                mma16(s[2*ntp],   qh[kt], kh0, kh1);
                mma16(s[2*ntp],   ql[kt], kh0, kh1);
                mma16(s[2*ntp],   qh[kt], kl0, kl1);
                mma16(s[2*ntp+1], qh[kt], kh2, kh3);
                mma16(s[2*ntp+1], ql[kt], kh2, kh3);
                mma16(s[2*ntp+1], qh[kt], kl2, kl3);
            }
        }

        // ---- fixed-offset softmax
#pragma unroll
        for (int nt = 0; nt < 8; nt++) {
            s[nt][0] = ex2(s[nt][0] - SMSHIFT);
            s[nt][1] = ex2(s[nt][1] - SMSHIFT);
            s[nt][2] = ex2(s[nt][2] - SMSHIFT);
            s[nt][3] = ex2(s[nt][3] - SMSHIFT);
            l0 += s[nt][0] + s[nt][1];
            l1 += s[nt][2] + s[nt][3];
        }

        // ---- O += P V: V ldsm issued FIRST (independent), then P packs, mma
#pragma unroll
        for (int kt = 0; kt < 4; kt++) {
            unsigned vh[8], vl[8];
#pragma unroll
            for (int ntp = 0; ntp < 2; ntp++) {
                const uint32_t va = base + 2 * KPS + voff + (uint32_t)(kt * 1280 + ntp * 32);
                ldsm_x4t(vh[4*ntp], vh[4*ntp+1], vh[4*ntp+2], vh[4*ntp+3], va);
                ldsm_x4t(vl[4*ntp], vl[4*ntp+1], vl[4*ntp+2], vl[4*ntp+3], va + KPS);
            }
            unsigned ph[4], pl[4];
#pragma unroll
            for (int half = 0; half < 2; half++) {
                const int nt = 2 * kt + half;
                const unsigned h01 = packbf(s[nt][0], s[nt][1]);
                const unsigned h23 = packbf(s[nt][2], s[nt][3]);
                const float2 f01 = __bfloat1622float2(*(const __nv_bfloat162*)&h01);
                const float2 f23 = __bfloat1622float2(*(const __nv_bfloat162*)&h23);
                ph[2 * half + 0] = h01;
                ph[2 * half + 1] = h23;
                pl[2 * half + 0] = packbf(s[nt][0] - f01.x, s[nt][1] - f01.y);
                pl[2 * half + 1] = packbf(s[nt][2] - f23.x, s[nt][3] - f23.y);
            }
#pragma unroll
            for (int ntp = 0; ntp < 2; ntp++) {
                mma16(o[2*ntp],   ph, vh[4*ntp+0], vh[4*ntp+1]);
                mma16(o[2*ntp],   pl, vh[4*ntp+0], vh[4*ntp+1]);
                mma16(o[2*ntp],   ph, vl[4*ntp+0], vl[4*ntp+1]);
                mma16(o[2*ntp+1], ph, vh[4*ntp+2], vh[4*ntp+3]);
                mma16(o[2*ntp+1], pl, vh[4*ntp+2], vh[4*ntp+3]);
                mma16(o[2*ntp+1], ph, vl[4*ntp+2], vl[4*ntp+3]);
            }
        }
        __syncthreads();
    }

    l0 += __shfl_xor_sync(0xffffffffu, l0, 1);
    l0 += __shfl_xor_sync(0xffffffffu, l0, 2);
    l1 += __shfl_xor_sync(0xffffffffu, l1, 1);
    l1 += __shfl_xor_sync(0xffffffffu, l1, 2);

    const float inv0 = 1.0f / l0, inv1 = 1.0f / l1;
#pragma unroll
    for (int dnt = 0; dnt < 4; dnt++) {
        const int c = h * HD + dnt * 8 + 2 * tig;
        {
            const float v0 = o[dnt][0] * inv0, v1 = o[dnt][1] * inv0;
            const float h0 = __bfloat162float(__float2bfloat16_rn(v0));
            const float h1 = __bfloat162float(__float2bfloat16_rn(v1));
            const size_t u = ((size_t)(((size_t)b << 10) + r0) * DIM + c) >> 1;
            ((unsigned*)outhi)[u] = packbf(v0, v1);
            ((unsigned*)outlo)[u] = packbf(v0 - h0, v1 - h1);
        }
        {
            const float v0 = o[dnt][2] * inv1, v1 = o[dnt][3] * inv1;
            const float h0 = __bfloat162float(__float2bfloat16_rn(v0));
            const float h1 = __bfloat162float(__float2bfloat16_rn(v1));
            const size_t u = ((size_t)(((size_t)b << 10) + r1) * DIM + c) >> 1;
            ((unsigned*)outhi)[u] = packbf(v0, v1);
            ((unsigned*)outlo)[u] = packbf(v0 - h0, v1 - h1);
        }
    }
}

// ---------------------------------------------------------------------------
extern "C" void kernel_launch(void* const* d_in, const int* in_sizes, int n_in,
                              void* d_out, int out_size)
{
    (void)in_sizes; (void)n_in; (void)out_size;
    const float* x      = (const float*)d_in[0];
    const float* qkv_w  = (const float*)d_in[1];
    const float* qkv_b  = (const float*)d_in[2];
    const float* proj_w = (const float*)d_in[3];
    const float* proj_b = (const float*)d_in[4];
    const float* temp   = (const float*)d_in[5];
    const float* qe     = (const float*)d_in[6];
    const float* c1w    = (const float*)d_in[7];
    const float* c1b    = (const float*)d_in[8];
    const float* c2w    = (const float*)d_in[9];
    const float* c2b    = (const float*)d_in[10];
    const float* rct    = (const float*)d_in[11];
    const int*   rpi    = (const int*)d_in[12];
    const float* sls    = (const float*)d_in[13];
    float* out = (float*)d_out;

    float *tt_s;
    bf16 *xhi, *xlo, *wqhi, *wqlo, *wphi, *wplo;
    bf16 *Qhi, *Qlo, *Khi, *Klo, *Vhi, *Vlo, *ahi, *alo, *rb_s;
    cudaGetSymbolAddress((void**)&tt_s,  g_tt);
    cudaGetSymbolAddress((void**)&xhi,  g_xhi);  cudaGetSymbolAddress((void**)&xlo,  g_xlo);
    cudaGetSymbolAddress((void**)&wqhi, g_wqhi); cudaGetSymbolAddress((void**)&wqlo, g_wqlo);
    cudaGetSymbolAddress((void**)&wphi, g_wphi); cudaGetSymbolAddress((void**)&wplo, g_wplo);
    cudaGetSymbolAddress((void**)&Qhi,  g_Qhi);  cudaGetSymbolAddress((void**)&Qlo,  g_Qlo);
    cudaGetSymbolAddress((void**)&Khi,  g_Khi);  cudaGetSymbolAddress((void**)&Klo,  g_Klo);
    cudaGetSymbolAddress((void**)&Vhi,  g_Vhi);  cudaGetSymbolAddress((void**)&Vlo,  g_Vlo);
    cudaGetSymbolAddress((void**)&ahi,  g_ahi);  cudaGetSymbolAddress((void**)&alo,  g_alo);
    cudaGetSymbolAddress((void**)&rb_s, g_rb);

    cudaFuncSetAttribute(attn_mma, cudaFuncAttributeMaxDynamicSharedMemorySize, ATTN_SMEM);
    cudaFuncSetAttribute(gemm_bs<0>, cudaFuncAttributeMaxDynamicSharedMemorySize, 2 * GBUF);
    cudaFuncSetAttribute(gemm_bs<1>, cudaFuncAttributeMaxDynamicSharedMemorySize, 2 * GBUF);

    // 0. fused prologue: splits + CPB MLP
    prologue_kernel<<<SPLITBLK + TBL, 256>>>(
        x, qkv_w, proj_w, xhi, xlo, wqhi, wqlo, wphi, wplo,
        rct, c1w, c1b, c2w, c2b, tt_s);

    // 1. qkv projection (fused norm/split epilogue) + trailing rb blocks
    //    rb blocks: y in [64, 64+86) -> 1032 slots covering 1024 q-rows
    gemm_bs<1><<<dim3(12, RB_YBASE + 86), 256, 2 * GBUF>>>(
        xhi, xlo, wqhi, wqlo, qkv_b, nullptr, B_ * NTOK, 3 * DIM, DIM,
        temp, qe, sls, Qhi, Qlo, Khi, Klo, Vhi, Vlo,
        rpi, tt_s, rb_s);

    // 2. fused attention (batch fastest for rb L2 reuse)
    attn_mma<<<dim3(B_, HEADS, NTOK / 128), 256, ATTN_SMEM>>>(
        Qhi, Qlo, Khi, Klo, Vhi, Vlo, rb_s, ahi, alo);

    // 3. output projection -> fp32 out
    gemm_bs<0><<<dim3(4, 64), 256, 2 * GBUF>>>(
        ahi, alo, wphi, wplo, proj_b, out, B_ * NTOK, DIM, DIM,
        nullptr, nullptr, nullptr,
        nullptr, nullptr, nullptr, nullptr, nullptr, nullptr,
        nullptr, nullptr, nullptr);
}